// round 13
// baseline (speedup 1.0000x reference)
#include <cuda_runtime.h>
#include <cuda_bf16.h>
#include <math.h>
#include <stdint.h>

// Problem dims
#define BB 4
#define SS 2048
#define II 512
#define DD 512
#define HH 8
#define HD 64
#define PP 720
#define NT (BB*SS)        // 8192 tokens
#define QKVW (3*DD)       // 1536

// ---------------- scratch (__device__ globals, no allocation) ----------------
__device__ __nv_bfloat16 g_qkvh[(size_t)NT * QKVW];
__device__ __nv_bfloat16 g_combh[(size_t)NT * DD];
__device__ __nv_bfloat16 g_combl[(size_t)NT * DD];
__device__ __nv_bfloat16 g_uph[(size_t)BB * PP * DD];
__device__ __nv_bfloat16 g_upl[(size_t)BB * PP * DD];
__device__ __nv_bfloat16 g_xh[(size_t)NT * II];
__device__ __nv_bfloat16 g_xl[(size_t)NT * II];
__device__ __nv_bfloat16 g_wph[(size_t)II * QKVW];
__device__ __nv_bfloat16 g_wpl[(size_t)II * QKVW];
__device__ __nv_bfloat16 g_wth[(size_t)PP * SS];
__device__ __nv_bfloat16 g_wtl[(size_t)PP * SS];
__device__ __nv_bfloat16 g_woh[(size_t)II * DD];   // natural [o][d] layout
__device__ __nv_bfloat16 g_wol[(size_t)II * DD];
__device__ float g_bp[QKVW];
__device__ float g_vsum[BB * HH * HD];             // per (b,h): column sums of V

// ---------------- helpers ----------------
__device__ __forceinline__ void mma_bf16(float* c, const uint32_t* a, const uint32_t* b) {
    asm volatile(
        "mma.sync.aligned.m16n8k16.row.col.f32.bf16.bf16.f32 "
        "{%0,%1,%2,%3}, {%4,%5,%6,%7}, {%8,%9}, {%0,%1,%2,%3};\n"
        : "+f"(c[0]), "+f"(c[1]), "+f"(c[2]), "+f"(c[3])
        : "r"(a[0]), "r"(a[1]), "r"(a[2]), "r"(a[3]), "r"(b[0]), "r"(b[1]));
}
__device__ __forceinline__ void split_bf16(float x, __nv_bfloat16& h, __nv_bfloat16& l) {
    h = __float2bfloat16(x);
    l = __float2bfloat16(x - __bfloat162float(h));
}
__device__ __forceinline__ uint32_t packb(__nv_bfloat16 a, __nv_bfloat16 b) {
    __nv_bfloat162 t; t.x = a; t.y = b;
    return *(uint32_t*)&t;
}
__device__ __forceinline__ void ldsm4(uint32_t* r, const __nv_bfloat16* p) {
    uint32_t a = (uint32_t)__cvta_generic_to_shared(p);
    asm volatile("ldmatrix.sync.aligned.m8n8.x4.shared.b16 {%0,%1,%2,%3}, [%4];\n"
        : "=r"(r[0]), "=r"(r[1]), "=r"(r[2]), "=r"(r[3]) : "r"(a));
}
__device__ __forceinline__ void ldsm4t(uint32_t* r, const __nv_bfloat16* p) {
    uint32_t a = (uint32_t)__cvta_generic_to_shared(p);
    asm volatile("ldmatrix.sync.aligned.m8n8.x4.trans.shared.b16 {%0,%1,%2,%3}, [%4];\n"
        : "=r"(r[0]), "=r"(r[1]), "=r"(r[2]), "=r"(r[3]) : "r"(a));
}
__device__ __forceinline__ void cp16(__nv_bfloat16* dst, const __nv_bfloat16* src) {
    uint32_t d = (uint32_t)__cvta_generic_to_shared(dst);
    asm volatile("cp.async.cg.shared.global [%0], [%1], 16;\n" :: "r"(d), "l"(src));
}
#define CP_COMMIT() asm volatile("cp.async.commit_group;\n")
#define CP_WAIT0()  asm volatile("cp.async.wait_group 0;\n")
#define CP_WAIT1()  asm volatile("cp.async.wait_group 1;\n")

// expm1 cubic: e^x - 1 ~= x(1 + x(1/2 + x/6)); |x|<=0.16 -> abs err <= 2e-5
__device__ __forceinline__ float expm1_poly(float x) {
    float i1 = fmaf(x, 0.16666667f, 0.5f);
    float i2 = fmaf(x, i1, 1.0f);
    return x * i2;
}

// ---------------- pack kernels ----------------
__global__ void pack_split4(const float* __restrict__ src,
                            __nv_bfloat16* __restrict__ dh,
                            __nv_bfloat16* __restrict__ dl, int n4)
{
    int i = blockIdx.x * blockDim.x + threadIdx.x;
    if (i >= n4) return;
    float4 v = ((const float4*)src)[i];
    __nv_bfloat16 h0,l0,h1,l1,h2,l2,h3,l3;
    split_bf16(v.x,h0,l0); split_bf16(v.y,h1,l1);
    split_bf16(v.z,h2,l2); split_bf16(v.w,h3,l3);
    ((uint32_t*)dh)[2*i  ] = packb(h0,h1);
    ((uint32_t*)dh)[2*i+1] = packb(h2,h3);
    ((uint32_t*)dl)[2*i  ] = packb(l0,l1);
    ((uint32_t*)dl)[2*i+1] = packb(l2,l3);
}

// vectorized over contiguous d (4 at a time)
__global__ void pack_qkv_w(const float* __restrict__ Wq,
                           const float* __restrict__ Wk,
                           const float* __restrict__ Wv,
                           __nv_bfloat16* __restrict__ dh,
                           __nv_bfloat16* __restrict__ dl)
{
    int idx = blockIdx.x * blockDim.x + threadIdx.x;   // over 3*512*512/4
    if (idx >= 3 * II * DD / 4) return;
    int e   = idx * 4;
    int m   = e / (II * DD);
    int rem = e % (II * DD);            // = h*(512*64) + i*64 + d
    int h   = rem / (II * HD);
    int i   = (rem / HD) % II;
    int d   = rem % HD;
    const float* src = (m == 0) ? Wq : (m == 1) ? Wk : Wv;
    float4 v = *(const float4*)(src + rem);
    __nv_bfloat16 h0,l0,h1,l1,h2,l2,h3,l3;
    split_bf16(v.x,h0,l0); split_bf16(v.y,h1,l1);
    split_bf16(v.z,h2,l2); split_bf16(v.w,h3,l3);
    long o = (long)i * QKVW + m * DD + h * HD + d;
    *(uint32_t*)(dh + o    ) = packb(h0,h1);
    *(uint32_t*)(dh + o + 2) = packb(h2,h3);
    *(uint32_t*)(dl + o    ) = packb(l0,l1);
    *(uint32_t*)(dl + o + 2) = packb(l2,l3);
}

__global__ void pack_qkv_b(const float* __restrict__ bq,
                           const float* __restrict__ bk,
                           const float* __restrict__ bv,
                           float* __restrict__ bp)
{
    int idx = blockIdx.x * blockDim.x + threadIdx.x;
    if (idx >= QKVW) return;
    int m = idx / DD;
    int r = idx % DD;
    const float* src = (m == 0) ? bq : (m == 1) ? bk : bv;
    bp[idx] = src[r];
}

// ---------------- V column sums: vsum[z][d] = sum_j V[z][j][d] ----------------
__global__ void vsum_kernel(const __nv_bfloat16* __restrict__ qkvh,
                            float* __restrict__ vsum)
{
    int z = blockIdx.x;                 // b*8 + h
    int d = threadIdx.x & 63;
    int rg = threadIdx.x >> 6;          // 0..3
    const __nv_bfloat16* v = qkvh + (long)(z >> 3) * SS * QKVW + (z & 7) * HD + 2 * DD;
    float s = 0.f;
    for (int j = rg; j < SS; j += 4)
        s += __bfloat162float(v[(long)j * QKVW + d]);
    __shared__ float red[256];
    red[threadIdx.x] = s;
    __syncthreads();
    if (rg == 0)
        vsum[z * HD + d] = red[d] + red[64 + d] + red[128 + d] + red[192 + d];
}

// ---------------- bf16-plane tensor-core GEMM ----------------
// b_kmajor: 0 -> B planes [k][n]; 1 -> B planes [n][k] k-contiguous.
// three_term: 0/1 explicit; 2 -> auto per block: n0 >= 2*DD uses 3-term (QKV merge).
#define GBM 128
#define GBN 64
#define GBK 32
#define ASTR 40
#define BSTR 72
#define A_TILE (GBM*ASTR)
#define B_TILE (GBN*ASTR)              // 2560, covers both layouts (kn needs 2304)
#define STAGE (2*A_TILE + 2*B_TILE)
#define GSMEM (2*STAGE*2)

__device__ __forceinline__ void gemm_load_stage(
    __nv_bfloat16* buf,
    const __nv_bfloat16* __restrict__ Ah, const __nv_bfloat16* __restrict__ Al,
    long a_off, int lda, int M, int m0,
    const __nv_bfloat16* __restrict__ Bh, const __nv_bfloat16* __restrict__ Bl,
    long b_off, int ldb, int n0, int k0, int tid, int three_term, int b_kmajor)
{
    #pragma unroll
    for (int i = 0; i < 4; i++) {
        int e = tid + i * 256;
        int plane = e >> 9;
        if (plane && !three_term) continue;
        int rem = e & 511;
        int m = rem >> 2;
        int seg = rem & 3;
        int mg = m0 + m; if (mg >= M) mg = M - 1;
        const __nv_bfloat16* src = (plane ? Al : Ah) + a_off + (long)mg * lda + k0 + seg * 8;
        cp16(buf + plane * A_TILE + m * ASTR + seg * 8, src);
    }
    if (b_kmajor) {
        #pragma unroll
        for (int i = 0; i < 2; i++) {
            int e = tid + i * 256;
            int plane = e >> 8;
            if (plane && !three_term) continue;
            int rem = e & 255;
            int n = rem >> 2;
            int seg = rem & 3;
            const __nv_bfloat16* src = (plane ? Bl : Bh) + b_off + (long)(n0 + n) * ldb + k0 + seg * 8;
            cp16(buf + 2 * A_TILE + plane * B_TILE + n * ASTR + seg * 8, src);
        }
    } else {
        #pragma unroll
        for (int i = 0; i < 2; i++) {
            int e = tid + i * 256;
            int plane = e >> 8;
            if (plane && !three_term) continue;
            int rem = e & 255;
            int k = rem >> 3;
            int seg = rem & 7;
            const __nv_bfloat16* src = (plane ? Bl : Bh) + b_off + (long)(k0 + k) * ldb + n0 + seg * 8;
            cp16(buf + 2 * A_TILE + plane * B_TILE + k * BSTR + seg * 8, src);
        }
    }
}

__global__ __launch_bounds__(256, 2)
void gemm_planes(
    int M, int N, int K,
    const __nv_bfloat16* __restrict__ Ah, const __nv_bfloat16* __restrict__ Al,
    long a_b, int lda,
    const __nv_bfloat16* __restrict__ Bh, const __nv_bfloat16* __restrict__ Bl,
    long b_b, int ldb,
    float* __restrict__ C, __nv_bfloat16* __restrict__ Ch, __nv_bfloat16* __restrict__ Cl,
    long c_b, int ldc,
    const float* __restrict__ bias, int bias_mode, int three_term, int b_kmajor)
{
    extern __shared__ __align__(16) __nv_bfloat16 gsm[];
    const int z = blockIdx.z;
    const long a_off = (long)z * a_b;
    const long b_off = (long)z * b_b;
    const long c_off = (long)z * c_b;
    const int m0 = blockIdx.y * GBM;
    const int n0 = blockIdx.x * GBN;
    const int tt = (three_term == 2) ? ((n0 >= 2 * DD) ? 1 : 0) : three_term;

    const int tid  = threadIdx.x;
    const int lane = tid & 31;
    const int warp = tid >> 5;
    const int wm = (warp & 3) * 32;
    const int wn = (warp >> 2) * 32;
    const int qr = lane >> 2;
    const int qc = (lane & 3) * 2;
    const int a_row = ((lane >> 3) & 1) * 8 + (lane & 7);
    const int a_col = (lane >> 4) * 8;
    const int b_row = ((lane >> 3) & 1) * 8 + (lane & 7);   // kn layout: k rows
    const int b_col = ((lane >> 4) & 1) * 8;
    const int bk_row = ((lane >> 4) & 1) * 8 + (lane & 7);  // nk layout: n rows
    const int bk_col = ((lane >> 3) & 1) * 8;

    float acc[2][4][4] = {};

    gemm_load_stage(gsm, Ah, Al, a_off, lda, M, m0, Bh, Bl, b_off, ldb, n0, 0, tid, tt, b_kmajor);
    CP_COMMIT();

    const int nstage = K / GBK;
    for (int s = 0; s < nstage; s++) {
        CP_WAIT0();
        __syncthreads();
        if (s + 1 < nstage) {
            gemm_load_stage(gsm + ((s + 1) & 1) * STAGE,
                            Ah, Al, a_off, lda, M, m0,
                            Bh, Bl, b_off, ldb, n0, (s + 1) * GBK, tid, tt, b_kmajor);
            CP_COMMIT();
        }
        const __nv_bfloat16* As = gsm + (s & 1) * STAGE;
        const __nv_bfloat16* Bs = As + 2 * A_TILE;

        #pragma unroll
        for (int ks = 0; ks < 2; ks++) {
            const int kc = ks * 16;
            uint32_t ah[2][4], al[2][4], bh[2][4], bl[2][4];
            #pragma unroll
            for (int mt = 0; mt < 2; mt++) {
                const __nv_bfloat16* base = As + (wm + mt * 16 + a_row) * ASTR + kc + a_col;
                ldsm4(ah[mt], base);
                if (tt) ldsm4(al[mt], base + A_TILE);
            }
            if (b_kmajor) {
                #pragma unroll
                for (int ng = 0; ng < 2; ng++) {
                    const __nv_bfloat16* base = Bs + (wn + ng * 16 + bk_row) * ASTR + kc + bk_col;
                    ldsm4(bh[ng], base);
                    if (tt) ldsm4(bl[ng], base + B_TILE);
                }
            } else {
                #pragma unroll
                for (int ng = 0; ng < 2; ng++) {
                    const __nv_bfloat16* base = Bs + (kc + b_row) * BSTR + wn + ng * 16 + b_col;
                    ldsm4t(bh[ng], base);
                    if (tt) ldsm4t(bl[ng], base + B_TILE);
                }
            }
            #pragma unroll
            for (int mt = 0; mt < 2; mt++)
                #pragma unroll
                for (int ng = 0; ng < 2; ng++) {
                    mma_bf16(acc[mt][2 * ng    ], ah[mt], bh[ng]);
                    mma_bf16(acc[mt][2 * ng + 1], ah[mt], bh[ng] + 2);
                    if (tt) {
                        mma_bf16(acc[mt][2 * ng    ], al[mt], bh[ng]);
                        mma_bf16(acc[mt][2 * ng    ], ah[mt], bl[ng]);
                        mma_bf16(acc[mt][2 * ng + 1], al[mt], bh[ng] + 2);
                        mma_bf16(acc[mt][2 * ng + 1], ah[mt], bl[ng] + 2);
                    }
                }
        }
        // NOTE: no end-of-loop __syncthreads needed — the top-of-iteration
        // barrier (after CP_WAIT0) orders buffer reuse across warps.
    }

    // --- epilogue
    #pragma unroll
    for (int mt = 0; mt < 2; mt++) {
        #pragma unroll
        for (int nt = 0; nt < 4; nt++) {
            int r0 = m0 + wm + mt * 16 + qr;
            int r1 = r0 + 8;
            int c  = n0 + wn + nt * 8 + qc;
            float bn0 = 0.f, bn1 = 0.f;
            if (bias_mode == 1) { bn0 = bias[c]; bn1 = bias[c + 1]; }
            float v00 = acc[mt][nt][0] + bn0;
            float v01 = acc[mt][nt][1] + bn1;
            float v10 = acc[mt][nt][2] + bn0;
            float v11 = acc[mt][nt][3] + bn1;
            if (bias_mode == 2) {
                if (r0 < M) { float bm = bias[r0]; v00 += bm; v01 += bm; }
                if (r1 < M) { float bm = bias[r1]; v10 += bm; v11 += bm; }
            }
            if (Ch && Cl) {
                __nv_bfloat16 h0, l0, h1, l1;
                if (r0 < M) {
                    split_bf16(v00, h0, l0); split_bf16(v01, h1, l1);
                    *(uint32_t*)(Ch + c_off + (long)r0 * ldc + c) = packb(h0, h1);
                    *(uint32_t*)(Cl + c_off + (long)r0 * ldc + c) = packb(l0, l1);
                }
                if (r1 < M) {
                    split_bf16(v10, h0, l0); split_bf16(v11, h1, l1);
                    *(uint32_t*)(Ch + c_off + (long)r1 * ldc + c) = packb(h0, h1);
                    *(uint32_t*)(Cl + c_off + (long)r1 * ldc + c) = packb(l0, l1);
                }
            } else if (Ch) {
                if (r0 < M)
                    *(uint32_t*)(Ch + c_off + (long)r0 * ldc + c) =
                        packb(__float2bfloat16(v00), __float2bfloat16(v01));
                if (r1 < M)
                    *(uint32_t*)(Ch + c_off + (long)r1 * ldc + c) =
                        packb(__float2bfloat16(v10), __float2bfloat16(v11));
            } else {
                if (r0 < M) {
                    C[c_off + (long)r0 * ldc + c    ] = v00;
                    C[c_off + (long)r0 * ldc + c + 1] = v01;
                }
                if (r1 < M) {
                    C[c_off + (long)r1 * ldc + c    ] = v10;
                    C[c_off + (long)r1 * ldc + c + 1] = v11;
                }
            }
        }
    }
}

// ---------------- fused flash attention ----------------
// 64 q-rows/CTA (4 warps). S = Q K^T 1-term; no-max softmax via expm1 poly;
// O = Vsum + T V with T = P-1 in bf16 (1-term). comb hi/lo output.
// 3-stage cp.async pipeline (depth-2 prefetch, wait_group 1).
#define FSC 0.015625f
#define VKP 72
#define FTILE (64*VKP)
#define NTILES 2          // Kh, Vh
#define NSTAGE 3
#define FSMEM (NSTAGE*NTILES*FTILE*2)

__device__ __forceinline__ void flash_load_chunk(
    __nv_bfloat16* buf,
    const __nv_bfloat16* __restrict__ qh_plane,
    long kbase, long vbase, int c, int tid)
{
    #pragma unroll
    for (int i = 0; i < 8; i++) {
        int e    = tid + i * 128;
        int tile = e >> 9;            // 0=Kh 1=Vh
        int rem  = e & 511;
        int row  = rem >> 3;
        int seg  = rem & 7;
        long off = ((tile == 0) ? kbase : vbase) + (long)(c * 64 + row) * QKVW + seg * 8;
        cp16(buf + tile * FTILE + row * VKP + seg * 8, qh_plane + off);
    }
}

__global__ __launch_bounds__(128, 4)
void flash_attn(const __nv_bfloat16* __restrict__ qh_plane,
                const float* __restrict__ vsum,
                __nv_bfloat16* __restrict__ combh,
                __nv_bfloat16* __restrict__ combl)
{
    extern __shared__ __align__(16) __nv_bfloat16 sm[];
    const int z = blockIdx.y;
    const int b = z >> 3, h = z & 7;
    const int m0 = blockIdx.x * 64;
    const int tid  = threadIdx.x;
    const int lane = tid & 31;
    const int warp = tid >> 5;
    const int qr = lane >> 2;
    const int qc = (lane & 3) * 2;

    const long zbase = (long)b * SS * QKVW + h * HD;
    const long kbase = zbase + DD;
    const long vbase = zbase + 2 * DD;

    const int r0 = m0 + warp * 16 + qr;
    uint32_t qh[4][4];
    #pragma unroll
    for (int ks = 0; ks < 4; ks++) {
        #pragma unroll
        for (int a = 0; a < 4; a++) {
            int row = r0 + (a & 1) * 8;
            int col = ks * 16 + qc + (a >> 1) * 8;
            qh[ks][a] = *(const uint32_t*)(qh_plane + zbase + (long)row * QKVW + col);
        }
    }

    float o[8][4] = {};
    float l0r = 0.f, l1r = 0.f;   // accumulate sum of t; add SS at end

    const int skey_off = ((lane >> 4) & 1) * 8 + (lane & 7);
    const int scol_off = ((lane >> 3) & 1) * 8;
    const int vkey_off = ((lane >> 3) & 1) * 8 + (lane & 7);
    const int vcol_off = ((lane >> 4) & 1) * 8;

    // prologue: prefetch chunks 0 and 1
    flash_load_chunk(sm, qh_plane, kbase, vbase, 0, tid);
    CP_COMMIT();
    flash_load_chunk(sm + NTILES * FTILE, qh_plane, kbase, vbase, 1, tid);
    CP_COMMIT();

    int buf_c = 0;
    for (int c = 0; c < SS / 64; c++) {
        CP_WAIT1();                 // chunk c complete; c+1 may still be in flight
        __syncthreads();
        const __nv_bfloat16* Kh_ = sm + buf_c * NTILES * FTILE;
        const __nv_bfloat16* Vh_ = Kh_ + FTILE;

        if (c + 2 < SS / 64) {
            int buf_n = buf_c + 2; if (buf_n >= NSTAGE) buf_n -= NSTAGE;
            flash_load_chunk(sm + buf_n * NTILES * FTILE,
                             qh_plane, kbase, vbase, c + 2, tid);
        }
        CP_COMMIT();                // commit (possibly empty) group to keep counts aligned

        // --- S = Q K^T (1-term)
        float s[8][4] = {};
        #pragma unroll
        for (int ks = 0; ks < 4; ks++) {
            const int kc = ks * 16;
            #pragma unroll
            for (int ntp = 0; ntp < 4; ntp++) {
                const __nv_bfloat16* base = Kh_ + (ntp * 16 + skey_off) * VKP + kc + scol_off;
                uint32_t bh[4];
                ldsm4(bh, base);
                mma_bf16(s[2 * ntp    ], qh[ks], bh);
                mma_bf16(s[2 * ntp + 1], qh[ks], bh + 2);
            }
        }

        // --- t = expm1(s/64) via cubic poly; accumulate sum of t
        float sum0 = 0.f, sum1 = 0.f;
        uint32_t ph[4][4];
        #pragma unroll
        for (int nt = 0; nt < 8; nt++) {
            float t0f = expm1_poly(s[nt][0] * FSC);
            float t1f = expm1_poly(s[nt][1] * FSC);
            float t2f = expm1_poly(s[nt][2] * FSC);
            float t3f = expm1_poly(s[nt][3] * FSC);
            sum0 += t0f + t1f; sum1 += t2f + t3f;
            __nv_bfloat16 t0 = __float2bfloat16(t0f);
            __nv_bfloat16 t1 = __float2bfloat16(t1f);
            __nv_bfloat16 t2 = __float2bfloat16(t2f);
            __nv_bfloat16 t3 = __float2bfloat16(t3f);
            int ks = nt >> 1, off = (nt & 1) * 2;
            ph[ks][off    ] = packb(t0, t1);
            ph[ks][off + 1] = packb(t2, t3);
        }
        l0r += sum0;
        l1r += sum1;

        // --- O += T V (1-term)
        #pragma unroll
        for (int ks = 0; ks < 4; ks++) {
            const int kc = ks * 16;
            #pragma unroll
            for (int ntp = 0; ntp < 4; ntp++) {
                const __nv_bfloat16* base = Vh_ + (kc + vkey_off) * VKP + ntp * 16 + vcol_off;
                uint32_t vh4[4];
                ldsm4t(vh4, base);
                mma_bf16(o[2 * ntp    ], ph[ks], vh4);
                mma_bf16(o[2 * ntp + 1], ph[ks], vh4 + 2);
            }
        }
        if (++buf_c >= NSTAGE) buf_c = 0;
        // no end sync: top barrier of next iter orders reuse (prefetch target
        // buf c+2 was last read at iter c-1, all warps past it).
    }

    // --- row sums across quad, l = SS + sum(t); add Vsum, normalize, write
    l0r += __shfl_xor_sync(0xffffffff, l0r, 1);
    l0r += __shfl_xor_sync(0xffffffff, l0r, 2);
    l1r += __shfl_xor_sync(0xffffffff, l1r, 1);
    l1r += __shfl_xor_sync(0xffffffff, l1r, 2);
    float inv0 = 1.f / (l0r + (float)SS), inv1 = 1.f / (l1r + (float)SS);
    const float* vs = vsum + z * HD;
    const long cbase = (long)b * SS * DD + h * HD;
    #pragma unroll
    for (int nt = 0; nt < 8; nt++) {
        int col = nt * 8 + qc;
        float vs0 = vs[col], vs1 = vs[col + 1];
        __nv_bfloat16 h0, l0, h1, l1;
        split_bf16((o[nt][0] + vs0) * inv0, h0, l0);
        split_bf16((o[nt][1] + vs1) * inv0, h1, l1);
        *(uint32_t*)(combh + cbase + (long)r0 * DD + col) = packb(h0, h1);
        *(uint32_t*)(combl + cbase + (long)r0 * DD + col) = packb(l0, l1);
        split_bf16((o[nt][2] + vs0) * inv1, h0, l0);
        split_bf16((o[nt][3] + vs1) * inv1, h1, l1);
        *(uint32_t*)(combh + cbase + (long)(r0 + 8) * DD + col) = packb(h0, h1);
        *(uint32_t*)(combl + cbase + (long)(r0 + 8) * DD + col) = packb(l0, l1);
    }
}

// ---------------- launch ----------------
extern "C" void kernel_launch(void* const* d_in, const int* in_sizes, int n_in,
                              void* d_out, int out_size)
{
    (void)in_sizes; (void)n_in; (void)out_size;
    const float* x  = (const float*)d_in[0];
    const float* Wq = (const float*)d_in[1];
    const float* bq = (const float*)d_in[2];
    const float* Wk = (const float*)d_in[3];
    const float* bk = (const float*)d_in[4];
    const float* Wv = (const float*)d_in[5];
    const float* bv = (const float*)d_in[6];
    const float* Wt = (const float*)d_in[7];
    const float* bt = (const float*)d_in[8];
    const float* Wo = (const float*)d_in[9];
    const float* bo = (const float*)d_in[10];
    float* out = (float*)d_out;

    __nv_bfloat16 *qkvh, *combh, *combl, *uph, *upl;
    __nv_bfloat16 *xh, *xl, *wph, *wpl, *wth, *wtl, *woh, *wol;
    float *bp, *vsum;
    cudaGetSymbolAddress((void**)&qkvh,  g_qkvh);
    cudaGetSymbolAddress((void**)&combh, g_combh);
    cudaGetSymbolAddress((void**)&combl, g_combl);
    cudaGetSymbolAddress((void**)&uph,   g_uph);
    cudaGetSymbolAddress((void**)&upl,   g_upl);
    cudaGetSymbolAddress((void**)&xh,    g_xh);
    cudaGetSymbolAddress((void**)&xl,    g_xl);
    cudaGetSymbolAddress((void**)&wph,   g_wph);
    cudaGetSymbolAddress((void**)&wpl,   g_wpl);
    cudaGetSymbolAddress((void**)&wth,   g_wth);
    cudaGetSymbolAddress((void**)&wtl,   g_wtl);
    cudaGetSymbolAddress((void**)&woh,   g_woh);
    cudaGetSymbolAddress((void**)&wol,   g_wol);
    cudaGetSymbolAddress((void**)&bp,    g_bp);
    cudaGetSymbolAddress((void**)&vsum,  g_vsum);

    static bool attr_set = false;
    if (!attr_set) {
        cudaFuncSetAttribute(flash_attn,
            cudaFuncAttributeMaxDynamicSharedMemorySize, FSMEM);
        cudaFuncSetAttribute(gemm_planes,
            cudaFuncAttributeMaxDynamicSharedMemorySize, GSMEM);
        attr_set = true;
    }

    // 0) packs
    pack_split4<<<(NT * II / 4 + 255) / 256, 256>>>(x, xh, xl, NT * II / 4);
    pack_qkv_w<<<(3 * II * DD / 4 + 255) / 256, 256>>>(Wq, Wk, Wv, wph, wpl);
    pack_split4<<<(PP * SS / 4 + 255) / 256, 256>>>(Wt, wth, wtl, PP * SS / 4);
    pack_split4<<<(II * DD / 4 + 255) / 256, 256>>>(Wo, woh, wol, II * DD / 4);
    pack_qkv_b<<<(QKVW + 255) / 256, 256>>>(bq, bk, bv, bp);

    // 1) merged QKV projection: [8192,512] @ [512,1536] -> qkvh (hi-only)
    //    QK columns (n0 < 1024): 1-term; V columns (n0 >= 1024): 3-term.
    {
        dim3 grid(QKVW / GBN, NT / GBM, 1);
        gemm_planes<<<grid, 256, GSMEM>>>(NT, QKVW, II,
            xh, xl, 0, II,
            wph, wpl, 0, QKVW,
            nullptr, qkvh, nullptr, 0, QKVW,
            bp, 1, 2, 0);
    }

    // 1c) V column sums per (b,h)
    vsum_kernel<<<BB * HH, 256>>>(qkvh, vsum);

    // 2) fused attention -> comb planes [B,S,D]
    {
        dim3 grid(SS / 64, BB * HH);
        flash_attn<<<grid, 128, FSMEM>>>(qkvh, vsum, combh, combl);
    }

    // 3) temporal: up[b,p,d] = sum_s Wt[p,s] * comb[b,s,d] + bt[p]  (3-term)
    {
        dim3 grid(DD / GBN, (PP + GBM - 1) / GBM, BB);
        gemm_planes<<<grid, 256, GSMEM>>>(PP, DD, SS,
            wth, wtl, 0, SS,
            combh, combl, (long)SS * DD, DD,
            nullptr, uph, upl, (long)PP * DD, DD,
            bt, 2, 1, 0);
    }

    // 4) out[b,p,o] = sum_d up[b,p,d] * Wo[o,d] + bo[o]  (3-term, B k-major)
    {
        dim3 grid(II / GBN, (PP + GBM - 1) / GBM, BB);
        gemm_planes<<<grid, 256, GSMEM>>>(PP, II, DD,
            uph, upl, (long)PP * DD, DD,
            woh, wol, 0, DD,
            out, nullptr, nullptr, (long)PP * II, II,
            bo, 1, 1, 1);
    }
}

// round 14
// speedup vs baseline: 1.0468x; 1.0468x over previous
#include <cuda_runtime.h>
#include <cuda_bf16.h>
#include <math.h>
#include <stdint.h>

// Problem dims
#define BB 4
#define SS 2048
#define II 512
#define DD 512
#define HH 8
#define HD 64
#define PP 720
#define NT (BB*SS)        // 8192 tokens
#define QKVW (3*DD)       // 1536

// ---------------- scratch (__device__ globals, no allocation) ----------------
__device__ __nv_bfloat16 g_qkvh[(size_t)NT * QKVW];
__device__ __nv_bfloat16 g_combh[(size_t)NT * DD];
__device__ __nv_bfloat16 g_combl[(size_t)NT * DD];
__device__ __nv_bfloat16 g_uph[(size_t)BB * PP * DD];
__device__ __nv_bfloat16 g_upl[(size_t)BB * PP * DD];
__device__ __nv_bfloat16 g_xh[(size_t)NT * II];
__device__ __nv_bfloat16 g_xl[(size_t)NT * II];
__device__ __nv_bfloat16 g_wph[(size_t)II * QKVW];
__device__ __nv_bfloat16 g_wpl[(size_t)II * QKVW];
__device__ __nv_bfloat16 g_wth[(size_t)PP * SS];
__device__ __nv_bfloat16 g_wtl[(size_t)PP * SS];
__device__ __nv_bfloat16 g_woh[(size_t)II * DD];   // natural [o][d] layout
__device__ __nv_bfloat16 g_wol[(size_t)II * DD];
__device__ float g_bp[QKVW];
__device__ float g_vsum[BB * HH * HD];
__device__ float g_scr[2 * (size_t)BB * PP * DD];  // split-K partials

// ---------------- helpers ----------------
__device__ __forceinline__ void mma_bf16(float* c, const uint32_t* a, const uint32_t* b) {
    asm volatile(
        "mma.sync.aligned.m16n8k16.row.col.f32.bf16.bf16.f32 "
        "{%0,%1,%2,%3}, {%4,%5,%6,%7}, {%8,%9}, {%0,%1,%2,%3};\n"
        : "+f"(c[0]), "+f"(c[1]), "+f"(c[2]), "+f"(c[3])
        : "r"(a[0]), "r"(a[1]), "r"(a[2]), "r"(a[3]), "r"(b[0]), "r"(b[1]));
}
__device__ __forceinline__ void split_bf16(float x, __nv_bfloat16& h, __nv_bfloat16& l) {
    h = __float2bfloat16(x);
    l = __float2bfloat16(x - __bfloat162float(h));
}
__device__ __forceinline__ uint32_t packb(__nv_bfloat16 a, __nv_bfloat16 b) {
    __nv_bfloat162 t; t.x = a; t.y = b;
    return *(uint32_t*)&t;
}
// pack two floats as bf16x2: lo in [15:0], hi in [31:16]
__device__ __forceinline__ uint32_t cvt_bf16x2(float lo, float hi) {
    uint32_t r;
    asm("cvt.rn.bf16x2.f32 %0, %1, %2;" : "=r"(r) : "f"(hi), "f"(lo));
    return r;
}
__device__ __forceinline__ void ldsm4(uint32_t* r, const __nv_bfloat16* p) {
    uint32_t a = (uint32_t)__cvta_generic_to_shared(p);
    asm volatile("ldmatrix.sync.aligned.m8n8.x4.shared.b16 {%0,%1,%2,%3}, [%4];\n"
        : "=r"(r[0]), "=r"(r[1]), "=r"(r[2]), "=r"(r[3]) : "r"(a));
}
__device__ __forceinline__ void ldsm4t(uint32_t* r, const __nv_bfloat16* p) {
    uint32_t a = (uint32_t)__cvta_generic_to_shared(p);
    asm volatile("ldmatrix.sync.aligned.m8n8.x4.trans.shared.b16 {%0,%1,%2,%3}, [%4];\n"
        : "=r"(r[0]), "=r"(r[1]), "=r"(r[2]), "=r"(r[3]) : "r"(a));
}
__device__ __forceinline__ void cp16(__nv_bfloat16* dst, const __nv_bfloat16* src) {
    uint32_t d = (uint32_t)__cvta_generic_to_shared(dst);
    asm volatile("cp.async.cg.shared.global [%0], [%1], 16;\n" :: "r"(d), "l"(src));
}
#define CP_COMMIT() asm volatile("cp.async.commit_group;\n")
#define CP_WAIT0()  asm volatile("cp.async.wait_group 0;\n")
#define CP_WAIT1()  asm volatile("cp.async.wait_group 1;\n")

// expm1 cubic: e^x - 1 ~= x(1 + x(1/2 + x/6)); |x|<=0.16 -> abs err <= 2e-5
__device__ __forceinline__ float expm1_poly(float x) {
    float i1 = fmaf(x, 0.16666667f, 0.5f);
    float i2 = fmaf(x, i1, 1.0f);
    return x * i2;
}

// ---------------- pack kernels ----------------
__global__ void pack_split4(const float* __restrict__ src,
                            __nv_bfloat16* __restrict__ dh,
                            __nv_bfloat16* __restrict__ dl, int n4)
{
    int i = blockIdx.x * blockDim.x + threadIdx.x;
    if (i >= n4) return;
    float4 v = ((const float4*)src)[i];
    __nv_bfloat16 h0,l0,h1,l1,h2,l2,h3,l3;
    split_bf16(v.x,h0,l0); split_bf16(v.y,h1,l1);
    split_bf16(v.z,h2,l2); split_bf16(v.w,h3,l3);
    ((uint32_t*)dh)[2*i  ] = packb(h0,h1);
    ((uint32_t*)dh)[2*i+1] = packb(h2,h3);
    ((uint32_t*)dl)[2*i  ] = packb(l0,l1);
    ((uint32_t*)dl)[2*i+1] = packb(l2,l3);
}

__global__ void pack_qkv_w(const float* __restrict__ Wq,
                           const float* __restrict__ Wk,
                           const float* __restrict__ Wv,
                           __nv_bfloat16* __restrict__ dh,
                           __nv_bfloat16* __restrict__ dl)
{
    int idx = blockIdx.x * blockDim.x + threadIdx.x;   // over 3*512*512/4
    if (idx >= 3 * II * DD / 4) return;
    int e   = idx * 4;
    int m   = e / (II * DD);
    int rem = e % (II * DD);            // = h*(512*64) + i*64 + d
    int h   = rem / (II * HD);
    int i   = (rem / HD) % II;
    int d   = rem % HD;
    const float* src = (m == 0) ? Wq : (m == 1) ? Wk : Wv;
    float4 v = *(const float4*)(src + rem);
    __nv_bfloat16 h0,l0,h1,l1,h2,l2,h3,l3;
    split_bf16(v.x,h0,l0); split_bf16(v.y,h1,l1);
    split_bf16(v.z,h2,l2); split_bf16(v.w,h3,l3);
    long o = (long)i * QKVW + m * DD + h * HD + d;
    *(uint32_t*)(dh + o    ) = packb(h0,h1);
    *(uint32_t*)(dh + o + 2) = packb(h2,h3);
    *(uint32_t*)(dl + o    ) = packb(l0,l1);
    *(uint32_t*)(dl + o + 2) = packb(l2,l3);
}

__global__ void pack_qkv_b(const float* __restrict__ bq,
                           const float* __restrict__ bk,
                           const float* __restrict__ bv,
                           float* __restrict__ bp)
{
    int idx = blockIdx.x * blockDim.x + threadIdx.x;
    if (idx >= QKVW) return;
    int m = idx / DD;
    int r = idx % DD;
    const float* src = (m == 0) ? bq : (m == 1) ? bk : bv;
    bp[idx] = src[r];
}

// ---------------- V column sums ----------------
__global__ void vsum_kernel(const __nv_bfloat16* __restrict__ qkvh,
                            float* __restrict__ vsum)
{
    int z = blockIdx.x;
    int d = threadIdx.x & 63;
    int rg = threadIdx.x >> 6;
    const __nv_bfloat16* v = qkvh + (long)(z >> 3) * SS * QKVW + (z & 7) * HD + 2 * DD;
    float s = 0.f;
    for (int j = rg; j < SS; j += 4)
        s += __bfloat162float(v[(long)j * QKVW + d]);
    __shared__ float red[256];
    red[threadIdx.x] = s;
    __syncthreads();
    if (rg == 0)
        vsum[z * HD + d] = red[d] + red[64 + d] + red[128 + d] + red[192 + d];
}

// ---------------- split-K combine epilogues ----------------
// up = scr0 + scr1 + bt[p] -> bf16 hi/lo planes
__global__ void up_pack(const float* __restrict__ scr,
                        const float* __restrict__ bt,
                        __nv_bfloat16* __restrict__ uh,
                        __nv_bfloat16* __restrict__ ul)
{
    int i = blockIdx.x * blockDim.x + threadIdx.x;
    if (i >= BB * PP * DD / 4) return;
    int e = i * 4;
    float bias = bt[(e / DD) % PP];
    float4 a = ((const float4*)scr)[i];
    float4 b = ((const float4*)(scr + (size_t)BB * PP * DD))[i];
    float v0 = a.x + b.x + bias, v1 = a.y + b.y + bias;
    float v2 = a.z + b.z + bias, v3 = a.w + b.w + bias;
    __nv_bfloat16 h0,l0,h1,l1,h2,l2,h3,l3;
    split_bf16(v0,h0,l0); split_bf16(v1,h1,l1);
    split_bf16(v2,h2,l2); split_bf16(v3,h3,l3);
    ((uint32_t*)uh)[2*i  ] = packb(h0,h1);
    ((uint32_t*)uh)[2*i+1] = packb(h2,h3);
    ((uint32_t*)ul)[2*i  ] = packb(l0,l1);
    ((uint32_t*)ul)[2*i+1] = packb(l2,l3);
}

// out = scr0 + scr1 + bo[o] -> fp32
__global__ void out_final(const float* __restrict__ scr,
                          const float* __restrict__ bo,
                          float* __restrict__ out)
{
    int i = blockIdx.x * blockDim.x + threadIdx.x;
    if (i >= BB * PP * II / 4) return;
    int e = i * 4;
    float4 bb = *(const float4*)(bo + (e % II));
    float4 a = ((const float4*)scr)[i];
    float4 b = ((const float4*)(scr + (size_t)BB * PP * II))[i];
    float4 r;
    r.x = a.x + b.x + bb.x; r.y = a.y + b.y + bb.y;
    r.z = a.z + b.z + bb.z; r.w = a.w + b.w + bb.w;
    ((float4*)out)[i] = r;
}

// ---------------- bf16-plane tensor-core GEMM ----------------
// Batched over blockIdx.z with split index: zo = z / z_inner (outer, e.g. batch),
// zi = z % z_inner (inner, e.g. K-half). Offsets: off = zo*_bo + zi*_bi.
// b_kmajor: 0 -> B planes [k][n]; 1 -> B planes [n][k] k-contiguous.
// three_term: 0/1 explicit; 2 -> auto per block (n0 >= 2*DD -> 3-term).
#define GBM 128
#define GBN 64
#define GBK 32
#define ASTR 40
#define BSTR 72
#define A_TILE (GBM*ASTR)
#define B_TILE (GBN*ASTR)
#define STAGE (2*A_TILE + 2*B_TILE)
#define GSMEM (2*STAGE*2)

__device__ __forceinline__ void gemm_load_stage(
    __nv_bfloat16* buf,
    const __nv_bfloat16* __restrict__ Ah, const __nv_bfloat16* __restrict__ Al,
    long a_off, int lda, int M, int m0,
    const __nv_bfloat16* __restrict__ Bh, const __nv_bfloat16* __restrict__ Bl,
    long b_off, int ldb, int n0, int k0, int tid, int three_term, int b_kmajor)
{
    #pragma unroll
    for (int i = 0; i < 4; i++) {
        int e = tid + i * 256;
        int plane = e >> 9;
        if (plane && !three_term) continue;
        int rem = e & 511;
        int m = rem >> 2;
        int seg = rem & 3;
        int mg = m0 + m; if (mg >= M) mg = M - 1;
        const __nv_bfloat16* src = (plane ? Al : Ah) + a_off + (long)mg * lda + k0 + seg * 8;
        cp16(buf + plane * A_TILE + m * ASTR + seg * 8, src);
    }
    if (b_kmajor) {
        #pragma unroll
        for (int i = 0; i < 2; i++) {
            int e = tid + i * 256;
            int plane = e >> 8;
            if (plane && !three_term) continue;
            int rem = e & 255;
            int n = rem >> 2;
            int seg = rem & 3;
            const __nv_bfloat16* src = (plane ? Bl : Bh) + b_off + (long)(n0 + n) * ldb + k0 + seg * 8;
            cp16(buf + 2 * A_TILE + plane * B_TILE + n * ASTR + seg * 8, src);
        }
    } else {
        #pragma unroll
        for (int i = 0; i < 2; i++) {
            int e = tid + i * 256;
            int plane = e >> 8;
            if (plane && !three_term) continue;
            int rem = e & 255;
            int k = rem >> 3;
            int seg = rem & 7;
            const __nv_bfloat16* src = (plane ? Bl : Bh) + b_off + (long)(k0 + k) * ldb + n0 + seg * 8;
            cp16(buf + 2 * A_TILE + plane * B_TILE + k * BSTR + seg * 8, src);
        }
    }
}

__global__ __launch_bounds__(256, 2)
void gemm_planes(
    int M, int N, int K,
    const __nv_bfloat16* __restrict__ Ah, const __nv_bfloat16* __restrict__ Al,
    long a_bo, long a_bi, int lda,
    const __nv_bfloat16* __restrict__ Bh, const __nv_bfloat16* __restrict__ Bl,
    long b_bo, long b_bi, int ldb,
    float* __restrict__ C, __nv_bfloat16* __restrict__ Ch, __nv_bfloat16* __restrict__ Cl,
    long c_bo, long c_bi, int ldc,
    const float* __restrict__ bias, int bias_mode, int three_term, int b_kmajor,
    int z_inner)
{
    extern __shared__ __align__(16) __nv_bfloat16 gsm[];
    const int z  = blockIdx.z;
    const int zo = z / z_inner;
    const int zi = z % z_inner;
    const long a_off = (long)zo * a_bo + (long)zi * a_bi;
    const long b_off = (long)zo * b_bo + (long)zi * b_bi;
    const long c_off = (long)zo * c_bo + (long)zi * c_bi;
    const int m0 = blockIdx.y * GBM;
    const int n0 = blockIdx.x * GBN;
    const int tt = (three_term == 2) ? ((n0 >= 2 * DD) ? 1 : 0) : three_term;

    const int tid  = threadIdx.x;
    const int lane = tid & 31;
    const int warp = tid >> 5;
    const int wm = (warp & 3) * 32;
    const int wn = (warp >> 2) * 32;
    const int qr = lane >> 2;
    const int qc = (lane & 3) * 2;
    const int a_row = ((lane >> 3) & 1) * 8 + (lane & 7);
    const int a_col = (lane >> 4) * 8;
    const int b_row = ((lane >> 3) & 1) * 8 + (lane & 7);
    const int b_col = ((lane >> 4) & 1) * 8;
    const int bk_row = ((lane >> 4) & 1) * 8 + (lane & 7);
    const int bk_col = ((lane >> 3) & 1) * 8;

    float acc[2][4][4] = {};

    gemm_load_stage(gsm, Ah, Al, a_off, lda, M, m0, Bh, Bl, b_off, ldb, n0, 0, tid, tt, b_kmajor);
    CP_COMMIT();

    const int nstage = K / GBK;
    for (int s = 0; s < nstage; s++) {
        CP_WAIT0();
        __syncthreads();
        if (s + 1 < nstage) {
            gemm_load_stage(gsm + ((s + 1) & 1) * STAGE,
                            Ah, Al, a_off, lda, M, m0,
                            Bh, Bl, b_off, ldb, n0, (s + 1) * GBK, tid, tt, b_kmajor);
            CP_COMMIT();
        }
        const __nv_bfloat16* As = gsm + (s & 1) * STAGE;
        const __nv_bfloat16* Bs = As + 2 * A_TILE;

        #pragma unroll
        for (int ks = 0; ks < 2; ks++) {
            const int kc = ks * 16;
            uint32_t ah[2][4], al[2][4], bh[2][4], bl[2][4];
            #pragma unroll
            for (int mt = 0; mt < 2; mt++) {
                const __nv_bfloat16* base = As + (wm + mt * 16 + a_row) * ASTR + kc + a_col;
                ldsm4(ah[mt], base);
                if (tt) ldsm4(al[mt], base + A_TILE);
            }
            if (b_kmajor) {
                #pragma unroll
                for (int ng = 0; ng < 2; ng++) {
                    const __nv_bfloat16* base = Bs + (wn + ng * 16 + bk_row) * ASTR + kc + bk_col;
                    ldsm4(bh[ng], base);
                    if (tt) ldsm4(bl[ng], base + B_TILE);
                }
            } else {
                #pragma unroll
                for (int ng = 0; ng < 2; ng++) {
                    const __nv_bfloat16* base = Bs + (kc + b_row) * BSTR + wn + ng * 16 + b_col;
                    ldsm4t(bh[ng], base);
                    if (tt) ldsm4t(bl[ng], base + B_TILE);
                }
            }
            #pragma unroll
            for (int mt = 0; mt < 2; mt++)
                #pragma unroll
                for (int ng = 0; ng < 2; ng++) {
                    mma_bf16(acc[mt][2 * ng    ], ah[mt], bh[ng]);
                    mma_bf16(acc[mt][2 * ng + 1], ah[mt], bh[ng] + 2);
                    if (tt) {
                        mma_bf16(acc[mt][2 * ng    ], al[mt], bh[ng]);
                        mma_bf16(acc[mt][2 * ng    ], ah[mt], bl[ng]);
                        mma_bf16(acc[mt][2 * ng + 1], al[mt], bh[ng] + 2);
                        mma_bf16(acc[mt][2 * ng + 1], ah[mt], bl[ng] + 2);
                    }
                }
        }
    }

    // --- epilogue
    #pragma unroll
    for (int mt = 0; mt < 2; mt++) {
        #pragma unroll
        for (int nt = 0; nt < 4; nt++) {
            int r0 = m0 + wm + mt * 16 + qr;
            int r1 = r0 + 8;
            int c  = n0 + wn + nt * 8 + qc;
            float bn0 = 0.f, bn1 = 0.f;
            if (bias_mode == 1) { bn0 = bias[c]; bn1 = bias[c + 1]; }
            float v00 = acc[mt][nt][0] + bn0;
            float v01 = acc[mt][nt][1] + bn1;
            float v10 = acc[mt][nt][2] + bn0;
            float v11 = acc[mt][nt][3] + bn1;
            if (bias_mode == 2) {
                if (r0 < M) { float bm = bias[r0]; v00 += bm; v01 += bm; }
                if (r1 < M) { float bm = bias[r1]; v10 += bm; v11 += bm; }
            }
            if (Ch && Cl) {
                __nv_bfloat16 h0, l0, h1, l1;
                if (r0 < M) {
                    split_bf16(v00, h0, l0); split_bf16(v01, h1, l1);
                    *(uint32_t*)(Ch + c_off + (long)r0 * ldc + c) = packb(h0, h1);
                    *(uint32_t*)(Cl + c_off + (long)r0 * ldc + c) = packb(l0, l1);
                }
                if (r1 < M) {
                    split_bf16(v10, h0, l0); split_bf16(v11, h1, l1);
                    *(uint32_t*)(Ch + c_off + (long)r1 * ldc + c) = packb(h0, h1);
                    *(uint32_t*)(Cl + c_off + (long)r1 * ldc + c) = packb(l0, l1);
                }
            } else if (Ch) {
                if (r0 < M)
                    *(uint32_t*)(Ch + c_off + (long)r0 * ldc + c) = cvt_bf16x2(v00, v01);
                if (r1 < M)
                    *(uint32_t*)(Ch + c_off + (long)r1 * ldc + c) = cvt_bf16x2(v10, v11);
            } else {
                if (r0 < M) {
                    C[c_off + (long)r0 * ldc + c    ] = v00;
                    C[c_off + (long)r0 * ldc + c + 1] = v01;
                }
                if (r1 < M) {
                    C[c_off + (long)r1 * ldc + c    ] = v10;
                    C[c_off + (long)r1 * ldc + c + 1] = v11;
                }
            }
        }
    }
}

// ---------------- fused flash attention ----------------
#define FSC 0.015625f
#define VKP 72
#define FTILE (64*VKP)
#define NTILES 2          // Kh, Vh
#define NSTAGE 3
#define FSMEM (NSTAGE*NTILES*FTILE*2)

__device__ __forceinline__ void flash_load_chunk(
    __nv_bfloat16* buf,
    const __nv_bfloat16* __restrict__ qh_plane,
    long kbase, long vbase, int c, int tid)
{
    #pragma unroll
    for (int i = 0; i < 8; i++) {
        int e    = tid + i * 128;
        int tile = e >> 9;
        int rem  = e & 511;
        int row  = rem >> 3;
        int seg  = rem & 7;
        long off = ((tile == 0) ? kbase : vbase) + (long)(c * 64 + row) * QKVW + seg * 8;
        cp16(buf + tile * FTILE + row * VKP + seg * 8, qh_plane + off);
    }
}

__global__ __launch_bounds__(128, 4)
void flash_attn(const __nv_bfloat16* __restrict__ qh_plane,
                const float* __restrict__ vsum,
                __nv_bfloat16* __restrict__ combh,
                __nv_bfloat16* __restrict__ combl)
{
    extern __shared__ __align__(16) __nv_bfloat16 sm[];
    const int z = blockIdx.y;
    const int b = z >> 3, h = z & 7;
    const int m0 = blockIdx.x * 64;
    const int tid  = threadIdx.x;
    const int lane = tid & 31;
    const int warp = tid >> 5;
    const int qr = lane >> 2;
    const int qc = (lane & 3) * 2;

    const long zbase = (long)b * SS * QKVW + h * HD;
    const long kbase = zbase + DD;
    const long vbase = zbase + 2 * DD;

    const int r0 = m0 + warp * 16 + qr;
    uint32_t qh[4][4];
    #pragma unroll
    for (int ks = 0; ks < 4; ks++) {
        #pragma unroll
        for (int a = 0; a < 4; a++) {
            int row = r0 + (a & 1) * 8;
            int col = ks * 16 + qc + (a >> 1) * 8;
            qh[ks][a] = *(const uint32_t*)(qh_plane + zbase + (long)row * QKVW + col);
        }
    }

    float o[8][4] = {};
    float l0r = 0.f, l1r = 0.f;

    const int skey_off = ((lane >> 4) & 1) * 8 + (lane & 7);
    const int scol_off = ((lane >> 3) & 1) * 8;
    const int vkey_off = ((lane >> 3) & 1) * 8 + (lane & 7);
    const int vcol_off = ((lane >> 4) & 1) * 8;

    flash_load_chunk(sm, qh_plane, kbase, vbase, 0, tid);
    CP_COMMIT();
    flash_load_chunk(sm + NTILES * FTILE, qh_plane, kbase, vbase, 1, tid);
    CP_COMMIT();

    int buf_c = 0;
    for (int c = 0; c < SS / 64; c++) {
        CP_WAIT1();
        __syncthreads();
        const __nv_bfloat16* Kh_ = sm + buf_c * NTILES * FTILE;
        const __nv_bfloat16* Vh_ = Kh_ + FTILE;

        if (c + 2 < SS / 64) {
            int buf_n = buf_c + 2; if (buf_n >= NSTAGE) buf_n -= NSTAGE;
            flash_load_chunk(sm + buf_n * NTILES * FTILE,
                             qh_plane, kbase, vbase, c + 2, tid);
        }
        CP_COMMIT();

        // --- S = Q K^T (1-term)
        float s[8][4] = {};
        #pragma unroll
        for (int ks = 0; ks < 4; ks++) {
            const int kc = ks * 16;
            #pragma unroll
            for (int ntp = 0; ntp < 4; ntp++) {
                const __nv_bfloat16* base = Kh_ + (ntp * 16 + skey_off) * VKP + kc + scol_off;
                uint32_t bh[4];
                ldsm4(bh, base);
                mma_bf16(s[2 * ntp    ], qh[ks], bh);
                mma_bf16(s[2 * ntp + 1], qh[ks], bh + 2);
            }
        }

        // --- t = expm1(s/64) poly; accumulate sum of t; pack via cvt.bf16x2
        float sum0 = 0.f, sum1 = 0.f;
        uint32_t ph[4][4];
        #pragma unroll
        for (int nt = 0; nt < 8; nt++) {
            float t0f = expm1_poly(s[nt][0] * FSC);
            float t1f = expm1_poly(s[nt][1] * FSC);
            float t2f = expm1_poly(s[nt][2] * FSC);
            float t3f = expm1_poly(s[nt][3] * FSC);
            sum0 += t0f + t1f; sum1 += t2f + t3f;
            int ks = nt >> 1, off = (nt & 1) * 2;
            ph[ks][off    ] = cvt_bf16x2(t0f, t1f);
            ph[ks][off + 1] = cvt_bf16x2(t2f, t3f);
        }
        l0r += sum0;
        l1r += sum1;

        // --- O += T V (1-term)
        #pragma unroll
        for (int ks = 0; ks < 4; ks++) {
            const int kc = ks * 16;
            #pragma unroll
            for (int ntp = 0; ntp < 4; ntp++) {
                const __nv_bfloat16* base = Vh_ + (kc + vkey_off) * VKP + ntp * 16 + vcol_off;
                uint32_t vh4[4];
                ldsm4t(vh4, base);
                mma_bf16(o[2 * ntp    ], ph[ks], vh4);
                mma_bf16(o[2 * ntp + 1], ph[ks], vh4 + 2);
            }
        }
        if (++buf_c >= NSTAGE) buf_c = 0;
    }

    // --- row sums, l = SS + sum(t); add Vsum, normalize, write hi/lo planes
    l0r += __shfl_xor_sync(0xffffffff, l0r, 1);
    l0r += __shfl_xor_sync(0xffffffff, l0r, 2);
    l1r += __shfl_xor_sync(0xffffffff, l1r, 1);
    l1r += __shfl_xor_sync(0xffffffff, l1r, 2);
    float inv0 = 1.f / (l0r + (float)SS), inv1 = 1.f / (l1r + (float)SS);
    const float* vs = vsum + z * HD;
    const long cbase = (long)b * SS * DD + h * HD;
    #pragma unroll
    for (int nt = 0; nt < 8; nt++) {
        int col = nt * 8 + qc;
        float vs0 = vs[col], vs1 = vs[col + 1];
        __nv_bfloat16 h0, l0, h1, l1;
        split_bf16((o[nt][0] + vs0) * inv0, h0, l0);
        split_bf16((o[nt][1] + vs1) * inv0, h1, l1);
        *(uint32_t*)(combh + cbase + (long)r0 * DD + col) = packb(h0, h1);
        *(uint32_t*)(combl + cbase + (long)r0 * DD + col) = packb(l0, l1);
        split_bf16((o[nt][2] + vs0) * inv1, h0, l0);
        split_bf16((o[nt][3] + vs1) * inv1, h1, l1);
        *(uint32_t*)(combh + cbase + (long)(r0 + 8) * DD + col) = packb(h0, h1);
        *(uint32_t*)(combl + cbase + (long)(r0 + 8) * DD + col) = packb(l0, l1);
    }
}

// ---------------- launch ----------------
extern "C" void kernel_launch(void* const* d_in, const int* in_sizes, int n_in,
                              void* d_out, int out_size)
{
    (void)in_sizes; (void)n_in; (void)out_size;
    const float* x  = (const float*)d_in[0];
    const float* Wq = (const float*)d_in[1];
    const float* bq = (const float*)d_in[2];
    const float* Wk = (const float*)d_in[3];
    const float* bk = (const float*)d_in[4];
    const float* Wv = (const float*)d_in[5];
    const float* bv = (const float*)d_in[6];
    const float* Wt = (const float*)d_in[7];
    const float* bt = (const float*)d_in[8];
    const float* Wo = (const float*)d_in[9];
    const float* bo = (const float*)d_in[10];
    float* out = (float*)d_out;

    __nv_bfloat16 *qkvh, *combh, *combl, *uph, *upl;
    __nv_bfloat16 *xh, *xl, *wph, *wpl, *wth, *wtl, *woh, *wol;
    float *bp, *vsum, *scr;
    cudaGetSymbolAddress((void**)&qkvh,  g_qkvh);
    cudaGetSymbolAddress((void**)&combh, g_combh);
    cudaGetSymbolAddress((void**)&combl, g_combl);
    cudaGetSymbolAddress((void**)&uph,   g_uph);
    cudaGetSymbolAddress((void**)&upl,   g_upl);
    cudaGetSymbolAddress((void**)&xh,    g_xh);
    cudaGetSymbolAddress((void**)&xl,    g_xl);
    cudaGetSymbolAddress((void**)&wph,   g_wph);
    cudaGetSymbolAddress((void**)&wpl,   g_wpl);
    cudaGetSymbolAddress((void**)&wth,   g_wth);
    cudaGetSymbolAddress((void**)&wtl,   g_wtl);
    cudaGetSymbolAddress((void**)&woh,   g_woh);
    cudaGetSymbolAddress((void**)&wol,   g_wol);
    cudaGetSymbolAddress((void**)&bp,    g_bp);
    cudaGetSymbolAddress((void**)&vsum,  g_vsum);
    cudaGetSymbolAddress((void**)&scr,   g_scr);

    static bool attr_set = false;
    if (!attr_set) {
        cudaFuncSetAttribute(flash_attn,
            cudaFuncAttributeMaxDynamicSharedMemorySize, FSMEM);
        cudaFuncSetAttribute(gemm_planes,
            cudaFuncAttributeMaxDynamicSharedMemorySize, GSMEM);
        attr_set = true;
    }

    // 0) packs
    pack_split4<<<(NT * II / 4 + 255) / 256, 256>>>(x, xh, xl, NT * II / 4);
    pack_qkv_w<<<(3 * II * DD / 4 + 255) / 256, 256>>>(Wq, Wk, Wv, wph, wpl);
    pack_split4<<<(PP * SS / 4 + 255) / 256, 256>>>(Wt, wth, wtl, PP * SS / 4);
    pack_split4<<<(II * DD / 4 + 255) / 256, 256>>>(Wo, woh, wol, II * DD / 4);
    pack_qkv_b<<<(QKVW + 255) / 256, 256>>>(bq, bk, bv, bp);

    // 1) merged QKV projection -> qkvh (hi-only); QK 1-term, V 3-term (auto)
    {
        dim3 grid(QKVW / GBN, NT / GBM, 1);
        gemm_planes<<<grid, 256, GSMEM>>>(NT, QKVW, II,
            xh, xl, 0, 0, II,
            wph, wpl, 0, 0, QKVW,
            nullptr, qkvh, nullptr, 0, 0, QKVW,
            bp, 1, 2, 0, 1);
    }

    // 1c) V column sums per (b,h)
    vsum_kernel<<<BB * HH, 256>>>(qkvh, vsum);

    // 2) fused attention -> comb planes [B,S,D]
    {
        dim3 grid(SS / 64, BB * HH);
        flash_attn<<<grid, 128, FSMEM>>>(qkvh, vsum, combh, combl);
    }

    // 3) temporal (3-term), split-K=2 -> fp32 scratch partials
    {
        dim3 grid(DD / GBN, (PP + GBM - 1) / GBM, BB * 2);
        gemm_planes<<<grid, 256, GSMEM>>>(PP, DD, SS / 2,
            wth, wtl, 0, SS / 2, SS,
            combh, combl, (long)SS * DD, (long)(SS / 2) * DD, DD,
            scr, nullptr, nullptr, (long)PP * DD, (long)BB * PP * DD, DD,
            nullptr, 0, 1, 0, 2);
    }
    // 3b) combine halves + bt -> up planes
    up_pack<<<(BB * PP * DD / 4 + 255) / 256, 256>>>(scr, bt, uph, upl);

    // 4) out (3-term, B k-major), split-K=2 -> fp32 scratch partials
    {
        dim3 grid(II / GBN, (PP + GBM - 1) / GBM, BB * 2);
        gemm_planes<<<grid, 256, GSMEM>>>(PP, II, DD / 2,
            uph, upl, (long)PP * DD, DD / 2, DD,
            woh, wol, 0, DD / 2, DD,
            scr, nullptr, nullptr, (long)PP * II, (long)BB * PP * II, II,
            nullptr, 0, 1, 1, 2);
    }
    // 4b) combine halves + bo -> fp32 out
    out_final<<<(BB * PP * II / 4 + 255) / 256, 256>>>(scr, bo, out);
}

// round 15
// speedup vs baseline: 1.0546x; 1.0075x over previous
#include <cuda_runtime.h>
#include <cuda_bf16.h>
#include <math.h>
#include <stdint.h>

// Problem dims
#define BB 4
#define SS 2048
#define II 512
#define DD 512
#define HH 8
#define HD 64
#define PP 720
#define NT (BB*SS)        // 8192 tokens
#define QKVW (3*DD)       // 1536
#define FSC 0.015625f     // 1/HD (power of two -> exact fold into Wq/bq)

// ---------------- scratch (__device__ globals, no allocation) ----------------
__device__ __nv_bfloat16 g_qkvh[(size_t)NT * QKVW];
__device__ __nv_bfloat16 g_combh[(size_t)NT * DD];
__device__ __nv_bfloat16 g_combl[(size_t)NT * DD];
__device__ __nv_bfloat16 g_uph[(size_t)BB * PP * DD];
__device__ __nv_bfloat16 g_upl[(size_t)BB * PP * DD];
__device__ __nv_bfloat16 g_xh[(size_t)NT * II];
__device__ __nv_bfloat16 g_xl[(size_t)NT * II];
__device__ __nv_bfloat16 g_wph[(size_t)II * QKVW];
__device__ __nv_bfloat16 g_wpl[(size_t)II * QKVW];
__device__ __nv_bfloat16 g_wth[(size_t)PP * SS];
__device__ __nv_bfloat16 g_wtl[(size_t)PP * SS];
__device__ __nv_bfloat16 g_woh[(size_t)II * DD];   // natural [o][d] layout
__device__ __nv_bfloat16 g_wol[(size_t)II * DD];
__device__ float g_bp[QKVW];
__device__ float g_vsum[BB * HH * HD];
__device__ float g_scr[2 * (size_t)BB * PP * DD];  // split-K partials

// ---------------- helpers ----------------
__device__ __forceinline__ void mma_bf16(float* c, const uint32_t* a, const uint32_t* b) {
    asm volatile(
        "mma.sync.aligned.m16n8k16.row.col.f32.bf16.bf16.f32 "
        "{%0,%1,%2,%3}, {%4,%5,%6,%7}, {%8,%9}, {%0,%1,%2,%3};\n"
        : "+f"(c[0]), "+f"(c[1]), "+f"(c[2]), "+f"(c[3])
        : "r"(a[0]), "r"(a[1]), "r"(a[2]), "r"(a[3]), "r"(b[0]), "r"(b[1]));
}
__device__ __forceinline__ void split_bf16(float x, __nv_bfloat16& h, __nv_bfloat16& l) {
    h = __float2bfloat16(x);
    l = __float2bfloat16(x - __bfloat162float(h));
}
__device__ __forceinline__ uint32_t packb(__nv_bfloat16 a, __nv_bfloat16 b) {
    __nv_bfloat162 t; t.x = a; t.y = b;
    return *(uint32_t*)&t;
}
__device__ __forceinline__ uint32_t cvt_bf16x2(float lo, float hi) {
    uint32_t r;
    asm("cvt.rn.bf16x2.f32 %0, %1, %2;" : "=r"(r) : "f"(hi), "f"(lo));
    return r;
}
__device__ __forceinline__ void ldsm4(uint32_t* r, const __nv_bfloat16* p) {
    uint32_t a = (uint32_t)__cvta_generic_to_shared(p);
    asm volatile("ldmatrix.sync.aligned.m8n8.x4.shared.b16 {%0,%1,%2,%3}, [%4];\n"
        : "=r"(r[0]), "=r"(r[1]), "=r"(r[2]), "=r"(r[3]) : "r"(a));
}
__device__ __forceinline__ void ldsm4t(uint32_t* r, const __nv_bfloat16* p) {
    uint32_t a = (uint32_t)__cvta_generic_to_shared(p);
    asm volatile("ldmatrix.sync.aligned.m8n8.x4.trans.shared.b16 {%0,%1,%2,%3}, [%4];\n"
        : "=r"(r[0]), "=r"(r[1]), "=r"(r[2]), "=r"(r[3]) : "r"(a));
}
__device__ __forceinline__ void cp16(__nv_bfloat16* dst, const __nv_bfloat16* src) {
    uint32_t d = (uint32_t)__cvta_generic_to_shared(dst);
    asm volatile("cp.async.cg.shared.global [%0], [%1], 16;\n" :: "r"(d), "l"(src));
}
#define CP_COMMIT() asm volatile("cp.async.commit_group;\n")
#define CP_WAIT0()  asm volatile("cp.async.wait_group 0;\n")
#define CP_WAIT1()  asm volatile("cp.async.wait_group 1;\n")

// expm1 cubic: e^x - 1 ~= x(1 + x(1/2 + x/6)); |x|<=0.16 -> abs err <= 2e-5
__device__ __forceinline__ float expm1_poly(float x) {
    float i1 = fmaf(x, 0.16666667f, 0.5f);
    float i2 = fmaf(x, i1, 1.0f);
    return x * i2;
}

// ---------------- pack kernels ----------------
__global__ void pack_split4(const float* __restrict__ src,
                            __nv_bfloat16* __restrict__ dh,
                            __nv_bfloat16* __restrict__ dl, int n4)
{
    int i = blockIdx.x * blockDim.x + threadIdx.x;
    if (i >= n4) return;
    float4 v = ((const float4*)src)[i];
    __nv_bfloat16 h0,l0,h1,l1,h2,l2,h3,l3;
    split_bf16(v.x,h0,l0); split_bf16(v.y,h1,l1);
    split_bf16(v.z,h2,l2); split_bf16(v.w,h3,l3);
    ((uint32_t*)dh)[2*i  ] = packb(h0,h1);
    ((uint32_t*)dh)[2*i+1] = packb(h2,h3);
    ((uint32_t*)dl)[2*i  ] = packb(l0,l1);
    ((uint32_t*)dl)[2*i+1] = packb(l2,l3);
}

// Wq scaled by FSC at pack time (power-of-two: exact)
__global__ void pack_qkv_w(const float* __restrict__ Wq,
                           const float* __restrict__ Wk,
                           const float* __restrict__ Wv,
                           __nv_bfloat16* __restrict__ dh,
                           __nv_bfloat16* __restrict__ dl)
{
    int idx = blockIdx.x * blockDim.x + threadIdx.x;   // over 3*512*512/4
    if (idx >= 3 * II * DD / 4) return;
    int e   = idx * 4;
    int m   = e / (II * DD);
    int rem = e % (II * DD);            // = h*(512*64) + i*64 + d
    int h   = rem / (II * HD);
    int i   = (rem / HD) % II;
    int d   = rem % HD;
    const float* src = (m == 0) ? Wq : (m == 1) ? Wk : Wv;
    float sc = (m == 0) ? FSC : 1.0f;
    float4 v = *(const float4*)(src + rem);
    __nv_bfloat16 h0,l0,h1,l1,h2,l2,h3,l3;
    split_bf16(v.x * sc,h0,l0); split_bf16(v.y * sc,h1,l1);
    split_bf16(v.z * sc,h2,l2); split_bf16(v.w * sc,h3,l3);
    long o = (long)i * QKVW + m * DD + h * HD + d;
    *(uint32_t*)(dh + o    ) = packb(h0,h1);
    *(uint32_t*)(dh + o + 2) = packb(h2,h3);
    *(uint32_t*)(dl + o    ) = packb(l0,l1);
    *(uint32_t*)(dl + o + 2) = packb(l2,l3);
}

__global__ void pack_qkv_b(const float* __restrict__ bq,
                           const float* __restrict__ bk,
                           const float* __restrict__ bv,
                           float* __restrict__ bp)
{
    int idx = blockIdx.x * blockDim.x + threadIdx.x;
    if (idx >= QKVW) return;
    int m = idx / DD;
    int r = idx % DD;
    const float* src = (m == 0) ? bq : (m == 1) ? bk : bv;
    bp[idx] = src[r] * ((m == 0) ? FSC : 1.0f);
}

// ---------------- V column sums ----------------
__global__ void vsum_kernel(const __nv_bfloat16* __restrict__ qkvh,
                            float* __restrict__ vsum)
{
    int z = blockIdx.x;
    int d = threadIdx.x & 63;
    int rg = threadIdx.x >> 6;
    const __nv_bfloat16* v = qkvh + (long)(z >> 3) * SS * QKVW + (z & 7) * HD + 2 * DD;
    float s = 0.f;
    for (int j = rg; j < SS; j += 4)
        s += __bfloat162float(v[(long)j * QKVW + d]);
    __shared__ float red[256];
    red[threadIdx.x] = s;
    __syncthreads();
    if (rg == 0)
        vsum[z * HD + d] = red[d] + red[64 + d] + red[128 + d] + red[192 + d];
}

// ---------------- split-K combine epilogues ----------------
__global__ void up_pack(const float* __restrict__ scr,
                        const float* __restrict__ bt,
                        __nv_bfloat16* __restrict__ uh,
                        __nv_bfloat16* __restrict__ ul)
{
    int i = blockIdx.x * blockDim.x + threadIdx.x;
    if (i >= BB * PP * DD / 4) return;
    int e = i * 4;
    float bias = bt[(e / DD) % PP];
    float4 a = ((const float4*)scr)[i];
    float4 b = ((const float4*)(scr + (size_t)BB * PP * DD))[i];
    float v0 = a.x + b.x + bias, v1 = a.y + b.y + bias;
    float v2 = a.z + b.z + bias, v3 = a.w + b.w + bias;
    __nv_bfloat16 h0,l0,h1,l1,h2,l2,h3,l3;
    split_bf16(v0,h0,l0); split_bf16(v1,h1,l1);
    split_bf16(v2,h2,l2); split_bf16(v3,h3,l3);
    ((uint32_t*)uh)[2*i  ] = packb(h0,h1);
    ((uint32_t*)uh)[2*i+1] = packb(h2,h3);
    ((uint32_t*)ul)[2*i  ] = packb(l0,l1);
    ((uint32_t*)ul)[2*i+1] = packb(l2,l3);
}

__global__ void out_final(const float* __restrict__ scr,
                          const float* __restrict__ bo,
                          float* __restrict__ out)
{
    int i = blockIdx.x * blockDim.x + threadIdx.x;
    if (i >= BB * PP * II / 4) return;
    int e = i * 4;
    float4 bb = *(const float4*)(bo + (e % II));
    float4 a = ((const float4*)scr)[i];
    float4 b = ((const float4*)(scr + (size_t)BB * PP * II))[i];
    float4 r;
    r.x = a.x + b.x + bb.x; r.y = a.y + b.y + bb.y;
    r.z = a.z + b.z + bb.z; r.w = a.w + b.w + bb.w;
    ((float4*)out)[i] = r;
}

// ---------------- bf16-plane tensor-core GEMM ----------------
#define GBM 128
#define GBN 64
#define GBK 32
#define ASTR 40
#define BSTR 72
#define A_TILE (GBM*ASTR)
#define B_TILE (GBN*ASTR)
#define STAGE (2*A_TILE + 2*B_TILE)
#define GSMEM (2*STAGE*2)

__device__ __forceinline__ void gemm_load_stage(
    __nv_bfloat16* buf,
    const __nv_bfloat16* __restrict__ Ah, const __nv_bfloat16* __restrict__ Al,
    long a_off, int lda, int M, int m0,
    const __nv_bfloat16* __restrict__ Bh, const __nv_bfloat16* __restrict__ Bl,
    long b_off, int ldb, int n0, int k0, int tid, int three_term, int b_kmajor)
{
    #pragma unroll
    for (int i = 0; i < 4; i++) {
        int e = tid + i * 256;
        int plane = e >> 9;
        if (plane && !three_term) continue;
        int rem = e & 511;
        int m = rem >> 2;
        int seg = rem & 3;
        int mg = m0 + m; if (mg >= M) mg = M - 1;
        const __nv_bfloat16* src = (plane ? Al : Ah) + a_off + (long)mg * lda + k0 + seg * 8;
        cp16(buf + plane * A_TILE + m * ASTR + seg * 8, src);
    }
    if (b_kmajor) {
        #pragma unroll
        for (int i = 0; i < 2; i++) {
            int e = tid + i * 256;
            int plane = e >> 8;
            if (plane && !three_term) continue;
            int rem = e & 255;
            int n = rem >> 2;
            int seg = rem & 3;
            const __nv_bfloat16* src = (plane ? Bl : Bh) + b_off + (long)(n0 + n) * ldb + k0 + seg * 8;
            cp16(buf + 2 * A_TILE + plane * B_TILE + n * ASTR + seg * 8, src);
        }
    } else {
        #pragma unroll
        for (int i = 0; i < 2; i++) {
            int e = tid + i * 256;
            int plane = e >> 8;
            if (plane && !three_term) continue;
            int rem = e & 255;
            int k = rem >> 3;
            int seg = rem & 7;
            const __nv_bfloat16* src = (plane ? Bl : Bh) + b_off + (long)(k0 + k) * ldb + n0 + seg * 8;
            cp16(buf + 2 * A_TILE + plane * B_TILE + k * BSTR + seg * 8, src);
        }
    }
}

__global__ __launch_bounds__(256, 2)
void gemm_planes(
    int M, int N, int K,
    const __nv_bfloat16* __restrict__ Ah, const __nv_bfloat16* __restrict__ Al,
    long a_bo, long a_bi, int lda,
    const __nv_bfloat16* __restrict__ Bh, const __nv_bfloat16* __restrict__ Bl,
    long b_bo, long b_bi, int ldb,
    float* __restrict__ C, __nv_bfloat16* __restrict__ Ch, __nv_bfloat16* __restrict__ Cl,
    long c_bo, long c_bi, int ldc,
    const float* __restrict__ bias, int bias_mode, int three_term, int b_kmajor,
    int z_inner)
{
    extern __shared__ __align__(16) __nv_bfloat16 gsm[];
    const int z  = blockIdx.z;
    const int zo = z / z_inner;
    const int zi = z % z_inner;
    const long a_off = (long)zo * a_bo + (long)zi * a_bi;
    const long b_off = (long)zo * b_bo + (long)zi * b_bi;
    const long c_off = (long)zo * c_bo + (long)zi * c_bi;
    const int m0 = blockIdx.y * GBM;
    const int n0 = blockIdx.x * GBN;
    const int tt = (three_term == 2) ? ((n0 >= 2 * DD) ? 1 : 0) : three_term;

    const int tid  = threadIdx.x;
    const int lane = tid & 31;
    const int warp = tid >> 5;
    const int wm = (warp & 3) * 32;
    const int wn = (warp >> 2) * 32;
    const int qr = lane >> 2;
    const int qc = (lane & 3) * 2;
    const int a_row = ((lane >> 3) & 1) * 8 + (lane & 7);
    const int a_col = (lane >> 4) * 8;
    const int b_row = ((lane >> 3) & 1) * 8 + (lane & 7);
    const int b_col = ((lane >> 4) & 1) * 8;
    const int bk_row = ((lane >> 4) & 1) * 8 + (lane & 7);
    const int bk_col = ((lane >> 3) & 1) * 8;

    float acc[2][4][4] = {};

    gemm_load_stage(gsm, Ah, Al, a_off, lda, M, m0, Bh, Bl, b_off, ldb, n0, 0, tid, tt, b_kmajor);
    CP_COMMIT();

    const int nstage = K / GBK;
    for (int s = 0; s < nstage; s++) {
        CP_WAIT0();
        __syncthreads();
        if (s + 1 < nstage) {
            gemm_load_stage(gsm + ((s + 1) & 1) * STAGE,
                            Ah, Al, a_off, lda, M, m0,
                            Bh, Bl, b_off, ldb, n0, (s + 1) * GBK, tid, tt, b_kmajor);
            CP_COMMIT();
        }
        const __nv_bfloat16* As = gsm + (s & 1) * STAGE;
        const __nv_bfloat16* Bs = As + 2 * A_TILE;

        #pragma unroll
        for (int ks = 0; ks < 2; ks++) {
            const int kc = ks * 16;
            uint32_t ah[2][4], al[2][4], bh[2][4], bl[2][4];
            #pragma unroll
            for (int mt = 0; mt < 2; mt++) {
                const __nv_bfloat16* base = As + (wm + mt * 16 + a_row) * ASTR + kc + a_col;
                ldsm4(ah[mt], base);
                if (tt) ldsm4(al[mt], base + A_TILE);
            }
            if (b_kmajor) {
                #pragma unroll
                for (int ng = 0; ng < 2; ng++) {
                    const __nv_bfloat16* base = Bs + (wn + ng * 16 + bk_row) * ASTR + kc + bk_col;
                    ldsm4(bh[ng], base);
                    if (tt) ldsm4(bl[ng], base + B_TILE);
                }
            } else {
                #pragma unroll
                for (int ng = 0; ng < 2; ng++) {
                    const __nv_bfloat16* base = Bs + (kc + b_row) * BSTR + wn + ng * 16 + b_col;
                    ldsm4t(bh[ng], base);
                    if (tt) ldsm4t(bl[ng], base + B_TILE);
                }
            }
            #pragma unroll
            for (int mt = 0; mt < 2; mt++)
                #pragma unroll
                for (int ng = 0; ng < 2; ng++) {
                    mma_bf16(acc[mt][2 * ng    ], ah[mt], bh[ng]);
                    mma_bf16(acc[mt][2 * ng + 1], ah[mt], bh[ng] + 2);
                    if (tt) {
                        mma_bf16(acc[mt][2 * ng    ], al[mt], bh[ng]);
                        mma_bf16(acc[mt][2 * ng    ], ah[mt], bl[ng]);
                        mma_bf16(acc[mt][2 * ng + 1], al[mt], bh[ng] + 2);
                        mma_bf16(acc[mt][2 * ng + 1], ah[mt], bl[ng] + 2);
                    }
                }
        }
    }

    // --- epilogue
    #pragma unroll
    for (int mt = 0; mt < 2; mt++) {
        #pragma unroll
        for (int nt = 0; nt < 4; nt++) {
            int r0 = m0 + wm + mt * 16 + qr;
            int r1 = r0 + 8;
            int c  = n0 + wn + nt * 8 + qc;
            float bn0 = 0.f, bn1 = 0.f;
            if (bias_mode == 1) { bn0 = bias[c]; bn1 = bias[c + 1]; }
            float v00 = acc[mt][nt][0] + bn0;
            float v01 = acc[mt][nt][1] + bn1;
            float v10 = acc[mt][nt][2] + bn0;
            float v11 = acc[mt][nt][3] + bn1;
            if (bias_mode == 2) {
                if (r0 < M) { float bm = bias[r0]; v00 += bm; v01 += bm; }
                if (r1 < M) { float bm = bias[r1]; v10 += bm; v11 += bm; }
            }
            if (Ch && Cl) {
                __nv_bfloat16 h0, l0, h1, l1;
                if (r0 < M) {
                    split_bf16(v00, h0, l0); split_bf16(v01, h1, l1);
                    *(uint32_t*)(Ch + c_off + (long)r0 * ldc + c) = packb(h0, h1);
                    *(uint32_t*)(Cl + c_off + (long)r0 * ldc + c) = packb(l0, l1);
                }
                if (r1 < M) {
                    split_bf16(v10, h0, l0); split_bf16(v11, h1, l1);
                    *(uint32_t*)(Ch + c_off + (long)r1 * ldc + c) = packb(h0, h1);
                    *(uint32_t*)(Cl + c_off + (long)r1 * ldc + c) = packb(l0, l1);
                }
            } else if (Ch) {
                if (r0 < M)
                    *(uint32_t*)(Ch + c_off + (long)r0 * ldc + c) = cvt_bf16x2(v00, v01);
                if (r1 < M)
                    *(uint32_t*)(Ch + c_off + (long)r1 * ldc + c) = cvt_bf16x2(v10, v11);
            } else {
                if (r0 < M) {
                    C[c_off + (long)r0 * ldc + c    ] = v00;
                    C[c_off + (long)r0 * ldc + c + 1] = v01;
                }
                if (r1 < M) {
                    C[c_off + (long)r1 * ldc + c    ] = v10;
                    C[c_off + (long)r1 * ldc + c + 1] = v11;
                }
            }
        }
    }
}

// ---------------- fused flash attention ----------------
// Q pre-scaled by 1/64 at pack time -> s is already the exp argument.
#define VKP 72
#define FTILE (64*VKP)
#define NTILES 2
#define NSTAGE 3
#define FSMEM (NSTAGE*NTILES*FTILE*2)

__device__ __forceinline__ void flash_load_chunk(
    __nv_bfloat16* buf,
    const __nv_bfloat16* __restrict__ qh_plane,
    long kbase, long vbase, int c, int tid)
{
    #pragma unroll
    for (int i = 0; i < 8; i++) {
        int e    = tid + i * 128;
        int tile = e >> 9;
        int rem  = e & 511;
        int row  = rem >> 3;
        int seg  = rem & 7;
        long off = ((tile == 0) ? kbase : vbase) + (long)(c * 64 + row) * QKVW + seg * 8;
        cp16(buf + tile * FTILE + row * VKP + seg * 8, qh_plane + off);
    }
}

__global__ __launch_bounds__(128, 4)
void flash_attn(const __nv_bfloat16* __restrict__ qh_plane,
                const float* __restrict__ vsum,
                __nv_bfloat16* __restrict__ combh,
                __nv_bfloat16* __restrict__ combl)
{
    extern __shared__ __align__(16) __nv_bfloat16 sm[];
    const int z = blockIdx.y;
    const int b = z >> 3, h = z & 7;
    const int m0 = blockIdx.x * 64;
    const int tid  = threadIdx.x;
    const int lane = tid & 31;
    const int warp = tid >> 5;
    const int qr = lane >> 2;
    const int qc = (lane & 3) * 2;

    const long zbase = (long)b * SS * QKVW + h * HD;
    const long kbase = zbase + DD;
    const long vbase = zbase + 2 * DD;

    const int r0 = m0 + warp * 16 + qr;
    uint32_t qh[4][4];
    #pragma unroll
    for (int ks = 0; ks < 4; ks++) {
        #pragma unroll
        for (int a = 0; a < 4; a++) {
            int row = r0 + (a & 1) * 8;
            int col = ks * 16 + qc + (a >> 1) * 8;
            qh[ks][a] = *(const uint32_t*)(qh_plane + zbase + (long)row * QKVW + col);
        }
    }

    float o[8][4] = {};
    float l0r = 0.f, l1r = 0.f;

    const int skey_off = ((lane >> 4) & 1) * 8 + (lane & 7);
    const int scol_off = ((lane >> 3) & 1) * 8;
    const int vkey_off = ((lane >> 3) & 1) * 8 + (lane & 7);
    const int vcol_off = ((lane >> 4) & 1) * 8;

    flash_load_chunk(sm, qh_plane, kbase, vbase, 0, tid);
    CP_COMMIT();
    flash_load_chunk(sm + NTILES * FTILE, qh_plane, kbase, vbase, 1, tid);
    CP_COMMIT();

    int buf_c = 0;
    for (int c = 0; c < SS / 64; c++) {
        CP_WAIT1();
        __syncthreads();
        const __nv_bfloat16* Kh_ = sm + buf_c * NTILES * FTILE;
        const __nv_bfloat16* Vh_ = Kh_ + FTILE;

        if (c + 2 < SS / 64) {
            int buf_n = buf_c + 2; if (buf_n >= NSTAGE) buf_n -= NSTAGE;
            flash_load_chunk(sm + buf_n * NTILES * FTILE,
                             qh_plane, kbase, vbase, c + 2, tid);
        }
        CP_COMMIT();

        // --- S = Q K^T (1-term; already scaled by 1/64 via Q)
        float s[8][4] = {};
        #pragma unroll
        for (int ks = 0; ks < 4; ks++) {
            const int kc = ks * 16;
            #pragma unroll
            for (int ntp = 0; ntp < 4; ntp++) {
                const __nv_bfloat16* base = Kh_ + (ntp * 16 + skey_off) * VKP + kc + scol_off;
                uint32_t bh[4];
                ldsm4(bh, base);
                mma_bf16(s[2 * ntp    ], qh[ks], bh);
                mma_bf16(s[2 * ntp + 1], qh[ks], bh + 2);
            }
        }

        // --- t = expm1(s) poly; accumulate sum of t; pack via cvt.bf16x2
        float sum0 = 0.f, sum1 = 0.f;
        uint32_t ph[4][4];
        #pragma unroll
        for (int nt = 0; nt < 8; nt++) {
            float t0f = expm1_poly(s[nt][0]);
            float t1f = expm1_poly(s[nt][1]);
            float t2f = expm1_poly(s[nt][2]);
            float t3f = expm1_poly(s[nt][3]);
            sum0 += t0f + t1f; sum1 += t2f + t3f;
            int ks = nt >> 1, off = (nt & 1) * 2;
            ph[ks][off    ] = cvt_bf16x2(t0f, t1f);
            ph[ks][off + 1] = cvt_bf16x2(t2f, t3f);
        }
        l0r += sum0;
        l1r += sum1;

        // --- O += T V (1-term)
        #pragma unroll
        for (int ks = 0; ks < 4; ks++) {
            const int kc = ks * 16;
            #pragma unroll
            for (int ntp = 0; ntp < 4; ntp++) {
                const __nv_bfloat16* base = Vh_ + (kc + vkey_off) * VKP + ntp * 16 + vcol_off;
                uint32_t vh4[4];
                ldsm4t(vh4, base);
                mma_bf16(o[2 * ntp    ], ph[ks], vh4);
                mma_bf16(o[2 * ntp + 1], ph[ks], vh4 + 2);
            }
        }
        if (++buf_c >= NSTAGE) buf_c = 0;
    }

    // --- row sums, l = SS + sum(t); add Vsum, normalize, write hi/lo planes
    l0r += __shfl_xor_sync(0xffffffff, l0r, 1);
    l0r += __shfl_xor_sync(0xffffffff, l0r, 2);
    l1r += __shfl_xor_sync(0xffffffff, l1r, 1);
    l1r += __shfl_xor_sync(0xffffffff, l1r, 2);
    float inv0 = 1.f / (l0r + (float)SS), inv1 = 1.f / (l1r + (float)SS);
    const float* vs = vsum + z * HD;
    const long cbase = (long)b * SS * DD + h * HD;
    #pragma unroll
    for (int nt = 0; nt < 8; nt++) {
        int col = nt * 8 + qc;
        float vs0 = vs[col], vs1 = vs[col + 1];
        __nv_bfloat16 h0, l0, h1, l1;
        split_bf16((o[nt][0] + vs0) * inv0, h0, l0);
        split_bf16((o[nt][1] + vs1) * inv0, h1, l1);
        *(uint32_t*)(combh + cbase + (long)r0 * DD + col) = packb(h0, h1);
        *(uint32_t*)(combl + cbase + (long)r0 * DD + col) = packb(l0, l1);
        split_bf16((o[nt][2] + vs0) * inv1, h0, l0);
        split_bf16((o[nt][3] + vs1) * inv1, h1, l1);
        *(uint32_t*)(combh + cbase + (long)(r0 + 8) * DD + col) = packb(h0, h1);
        *(uint32_t*)(combl + cbase + (long)(r0 + 8) * DD + col) = packb(l0, l1);
    }
}

// ---------------- launch ----------------
extern "C" void kernel_launch(void* const* d_in, const int* in_sizes, int n_in,
                              void* d_out, int out_size)
{
    (void)in_sizes; (void)n_in; (void)out_size;
    const float* x  = (const float*)d_in[0];
    const float* Wq = (const float*)d_in[1];
    const float* bq = (const float*)d_in[2];
    const float* Wk = (const float*)d_in[3];
    const float* bk = (const float*)d_in[4];
    const float* Wv = (const float*)d_in[5];
    const float* bv = (const float*)d_in[6];
    const float* Wt = (const float*)d_in[7];
    const float* bt = (const float*)d_in[8];
    const float* Wo = (const float*)d_in[9];
    const float* bo = (const float*)d_in[10];
    float* out = (float*)d_out;

    __nv_bfloat16 *qkvh, *combh, *combl, *uph, *upl;
    __nv_bfloat16 *xh, *xl, *wph, *wpl, *wth, *wtl, *woh, *wol;
    float *bp, *vsum, *scr;
    cudaGetSymbolAddress((void**)&qkvh,  g_qkvh);
    cudaGetSymbolAddress((void**)&combh, g_combh);
    cudaGetSymbolAddress((void**)&combl, g_combl);
    cudaGetSymbolAddress((void**)&uph,   g_uph);
    cudaGetSymbolAddress((void**)&upl,   g_upl);
    cudaGetSymbolAddress((void**)&xh,    g_xh);
    cudaGetSymbolAddress((void**)&xl,    g_xl);
    cudaGetSymbolAddress((void**)&wph,   g_wph);
    cudaGetSymbolAddress((void**)&wpl,   g_wpl);
    cudaGetSymbolAddress((void**)&wth,   g_wth);
    cudaGetSymbolAddress((void**)&wtl,   g_wtl);
    cudaGetSymbolAddress((void**)&woh,   g_woh);
    cudaGetSymbolAddress((void**)&wol,   g_wol);
    cudaGetSymbolAddress((void**)&bp,    g_bp);
    cudaGetSymbolAddress((void**)&vsum,  g_vsum);
    cudaGetSymbolAddress((void**)&scr,   g_scr);

    static cudaStream_t s2 = nullptr;
    static cudaEvent_t evF = nullptr, evJ = nullptr;
    static bool attr_set = false;
    if (!attr_set) {
        cudaFuncSetAttribute(flash_attn,
            cudaFuncAttributeMaxDynamicSharedMemorySize, FSMEM);
        cudaFuncSetAttribute(gemm_planes,
            cudaFuncAttributeMaxDynamicSharedMemorySize, GSMEM);
        cudaStreamCreateWithFlags(&s2, cudaStreamNonBlocking);
        cudaEventCreateWithFlags(&evF, cudaEventDisableTiming);
        cudaEventCreateWithFlags(&evJ, cudaEventDisableTiming);
        attr_set = true;
    }

    // fork: Wt/Wo packs on side stream (overlap with QKV pipeline)
    cudaEventRecord(evF, 0);
    cudaStreamWaitEvent(s2, evF, 0);
    pack_split4<<<(PP * SS / 4 + 255) / 256, 256, 0, s2>>>(Wt, wth, wtl, PP * SS / 4);
    pack_split4<<<(II * DD / 4 + 255) / 256, 256, 0, s2>>>(Wo, woh, wol, II * DD / 4);
    cudaEventRecord(evJ, s2);

    // main stream: x / QKV-weight packs
    pack_split4<<<(NT * II / 4 + 255) / 256, 256>>>(x, xh, xl, NT * II / 4);
    pack_qkv_w<<<(3 * II * DD / 4 + 255) / 256, 256>>>(Wq, Wk, Wv, wph, wpl);
    pack_qkv_b<<<(QKVW + 255) / 256, 256>>>(bq, bk, bv, bp);

    // 1) merged QKV projection -> qkvh (hi-only); QK 1-term, V 3-term (auto)
    {
        dim3 grid(QKVW / GBN, NT / GBM, 1);
        gemm_planes<<<grid, 256, GSMEM>>>(NT, QKVW, II,
            xh, xl, 0, 0, II,
            wph, wpl, 0, 0, QKVW,
            nullptr, qkvh, nullptr, 0, 0, QKVW,
            bp, 1, 2, 0, 1);
    }

    // 1c) V column sums per (b,h)
    vsum_kernel<<<BB * HH, 256>>>(qkvh, vsum);

    // 2) fused attention -> comb planes [B,S,D]
    {
        dim3 grid(SS / 64, BB * HH);
        flash_attn<<<grid, 128, FSMEM>>>(qkvh, vsum, combh, combl);
    }

    // join: Wt/Wo packs must be done before tail GEMMs
    cudaStreamWaitEvent(0, evJ, 0);

    // 3) temporal (3-term), split-K=2 -> fp32 scratch partials
    {
        dim3 grid(DD / GBN, (PP + GBM - 1) / GBM, BB * 2);
        gemm_planes<<<grid, 256, GSMEM>>>(PP, DD, SS / 2,
            wth, wtl, 0, SS / 2, SS,
            combh, combl, (long)SS * DD, (long)(SS / 2) * DD, DD,
            scr, nullptr, nullptr, (long)PP * DD, (long)BB * PP * DD, DD,
            nullptr, 0, 1, 0, 2);
    }
    up_pack<<<(BB * PP * DD / 4 + 255) / 256, 256>>>(scr, bt, uph, upl);

    // 4) out (3-term, B k-major), split-K=2 -> fp32 scratch partials
    {
        dim3 grid(II / GBN, (PP + GBM - 1) / GBM, BB * 2);
        gemm_planes<<<grid, 256, GSMEM>>>(PP, II, DD / 2,
            uph, upl, (long)PP * DD, DD / 2, DD,
            woh, wol, 0, DD / 2, DD,
            scr, nullptr, nullptr, (long)PP * II, (long)BB * PP * II, II,
            nullptr, 0, 1, 1, 2);
    }
    out_final<<<(BB * PP * II / 4 + 255) / 256, 256>>>(scr, bo, out);
}

// round 16
// speedup vs baseline: 1.0606x; 1.0056x over previous
#include <cuda_runtime.h>
#include <cuda_bf16.h>
#include <math.h>
#include <stdint.h>

// Problem dims
#define BB 4
#define SS 2048
#define II 512
#define DD 512
#define HH 8
#define HD 64
#define PP 720
#define NT (BB*SS)        // 8192 tokens
#define QKVW (3*DD)       // 1536
#define FSC 0.015625f     // 1/HD (power of two -> exact fold into Wq/bq)

// ---------------- scratch (__device__ globals, no allocation) ----------------
__device__ __nv_bfloat16 g_qkvh[(size_t)NT * QKVW];
__device__ __nv_bfloat16 g_combh[(size_t)NT * DD];
__device__ __nv_bfloat16 g_combl[(size_t)NT * DD];
__device__ __nv_bfloat16 g_uph[(size_t)BB * PP * DD];
__device__ __nv_bfloat16 g_upl[(size_t)BB * PP * DD];
__device__ __nv_bfloat16 g_xh[(size_t)NT * II];
__device__ __nv_bfloat16 g_xl[(size_t)NT * II];
__device__ __nv_bfloat16 g_wph[(size_t)II * QKVW];
__device__ __nv_bfloat16 g_wpl[(size_t)II * QKVW];
__device__ __nv_bfloat16 g_wth[(size_t)PP * SS];
__device__ __nv_bfloat16 g_wtl[(size_t)PP * SS];
__device__ __nv_bfloat16 g_woh[(size_t)II * DD];   // natural [o][d] layout
__device__ __nv_bfloat16 g_wol[(size_t)II * DD];
__device__ float g_bp[QKVW];
__device__ float g_vsum[BB * HH * HD];
__device__ float g_scr[2 * (size_t)BB * PP * DD];  // split-K partials

// ---------------- helpers ----------------
__device__ __forceinline__ void mma_bf16(float* c, const uint32_t* a, const uint32_t* b) {
    asm volatile(
        "mma.sync.aligned.m16n8k16.row.col.f32.bf16.bf16.f32 "
        "{%0,%1,%2,%3}, {%4,%5,%6,%7}, {%8,%9}, {%0,%1,%2,%3};\n"
        : "+f"(c[0]), "+f"(c[1]), "+f"(c[2]), "+f"(c[3])
        : "r"(a[0]), "r"(a[1]), "r"(a[2]), "r"(a[3]), "r"(b[0]), "r"(b[1]));
}
__device__ __forceinline__ void split_bf16(float x, __nv_bfloat16& h, __nv_bfloat16& l) {
    h = __float2bfloat16(x);
    l = __float2bfloat16(x - __bfloat162float(h));
}
__device__ __forceinline__ uint32_t packb(__nv_bfloat16 a, __nv_bfloat16 b) {
    __nv_bfloat162 t; t.x = a; t.y = b;
    return *(uint32_t*)&t;
}
__device__ __forceinline__ uint32_t cvt_bf16x2(float lo, float hi) {
    uint32_t r;
    asm("cvt.rn.bf16x2.f32 %0, %1, %2;" : "=r"(r) : "f"(hi), "f"(lo));
    return r;
}
// ---- packed f32x2 (per-lane IEEE identical to scalar) ----
__device__ __forceinline__ uint64_t pk2(float lo, float hi) {
    uint64_t r;
    asm("mov.b64 %0, {%1, %2};" : "=l"(r) : "f"(lo), "f"(hi));
    return r;
}
__device__ __forceinline__ void unpk2(uint64_t v, float& lo, float& hi) {
    asm("mov.b64 {%0, %1}, %2;" : "=f"(lo), "=f"(hi) : "l"(v));
}
__device__ __forceinline__ uint64_t fma2(uint64_t a, uint64_t b, uint64_t c) {
    uint64_t r;
    asm("fma.rn.f32x2 %0, %1, %2, %3;" : "=l"(r) : "l"(a), "l"(b), "l"(c));
    return r;
}
__device__ __forceinline__ uint64_t mul2(uint64_t a, uint64_t b) {
    uint64_t r;
    asm("mul.rn.f32x2 %0, %1, %2;" : "=l"(r) : "l"(a), "l"(b));
    return r;
}
__device__ __forceinline__ uint64_t add2(uint64_t a, uint64_t b) {
    uint64_t r;
    asm("add.rn.f32x2 %0, %1, %2;" : "=l"(r) : "l"(a), "l"(b));
    return r;
}
// bf16x2 from packed pair: low lane -> [15:0]
__device__ __forceinline__ uint32_t cvt_bf16x2_p(uint64_t p) {
    uint32_t r;
    asm("{\n\t.reg .f32 lo, hi;\n\tmov.b64 {lo, hi}, %1;\n\t"
        "cvt.rn.bf16x2.f32 %0, hi, lo;\n\t}" : "=r"(r) : "l"(p));
    return r;
}
// packed expm1 cubic: e^x-1 ~= x(1 + x(1/2 + x/6)) per lane (exact scalar match)
__device__ __forceinline__ uint64_t expm1_poly2(uint64_t x) {
    const uint64_t C16 = pk2(0.16666667f, 0.16666667f);
    const uint64_t C05 = pk2(0.5f, 0.5f);
    const uint64_t C1  = pk2(1.0f, 1.0f);
    uint64_t i1 = fma2(x, C16, C05);
    uint64_t i2 = fma2(x, i1, C1);
    return mul2(x, i2);
}
__device__ __forceinline__ void ldsm4(uint32_t* r, const __nv_bfloat16* p) {
    uint32_t a = (uint32_t)__cvta_generic_to_shared(p);
    asm volatile("ldmatrix.sync.aligned.m8n8.x4.shared.b16 {%0,%1,%2,%3}, [%4];\n"
        : "=r"(r[0]), "=r"(r[1]), "=r"(r[2]), "=r"(r[3]) : "r"(a));
}
__device__ __forceinline__ void ldsm4t(uint32_t* r, const __nv_bfloat16* p) {
    uint32_t a = (uint32_t)__cvta_generic_to_shared(p);
    asm volatile("ldmatrix.sync.aligned.m8n8.x4.trans.shared.b16 {%0,%1,%2,%3}, [%4];\n"
        : "=r"(r[0]), "=r"(r[1]), "=r"(r[2]), "=r"(r[3]) : "r"(a));
}
__device__ __forceinline__ void cp16(__nv_bfloat16* dst, const __nv_bfloat16* src) {
    uint32_t d = (uint32_t)__cvta_generic_to_shared(dst);
    asm volatile("cp.async.cg.shared.global [%0], [%1], 16;\n" :: "r"(d), "l"(src));
}
#define CP_COMMIT() asm volatile("cp.async.commit_group;\n")
#define CP_WAIT0()  asm volatile("cp.async.wait_group 0;\n")
#define CP_WAIT1()  asm volatile("cp.async.wait_group 1;\n")

// ---------------- pack kernels ----------------
__global__ void pack_split4(const float* __restrict__ src,
                            __nv_bfloat16* __restrict__ dh,
                            __nv_bfloat16* __restrict__ dl, int n4)
{
    int i = blockIdx.x * blockDim.x + threadIdx.x;
    if (i >= n4) return;
    float4 v = ((const float4*)src)[i];
    __nv_bfloat16 h0,l0,h1,l1,h2,l2,h3,l3;
    split_bf16(v.x,h0,l0); split_bf16(v.y,h1,l1);
    split_bf16(v.z,h2,l2); split_bf16(v.w,h3,l3);
    ((uint32_t*)dh)[2*i  ] = packb(h0,h1);
    ((uint32_t*)dh)[2*i+1] = packb(h2,h3);
    ((uint32_t*)dl)[2*i  ] = packb(l0,l1);
    ((uint32_t*)dl)[2*i+1] = packb(l2,l3);
}

// Wq scaled by FSC at pack time (power-of-two: exact)
__global__ void pack_qkv_w(const float* __restrict__ Wq,
                           const float* __restrict__ Wk,
                           const float* __restrict__ Wv,
                           __nv_bfloat16* __restrict__ dh,
                           __nv_bfloat16* __restrict__ dl)
{
    int idx = blockIdx.x * blockDim.x + threadIdx.x;   // over 3*512*512/4
    if (idx >= 3 * II * DD / 4) return;
    int e   = idx * 4;
    int m   = e / (II * DD);
    int rem = e % (II * DD);            // = h*(512*64) + i*64 + d
    int h   = rem / (II * HD);
    int i   = (rem / HD) % II;
    int d   = rem % HD;
    const float* src = (m == 0) ? Wq : (m == 1) ? Wk : Wv;
    float sc = (m == 0) ? FSC : 1.0f;
    float4 v = *(const float4*)(src + rem);
    __nv_bfloat16 h0,l0,h1,l1,h2,l2,h3,l3;
    split_bf16(v.x * sc,h0,l0); split_bf16(v.y * sc,h1,l1);
    split_bf16(v.z * sc,h2,l2); split_bf16(v.w * sc,h3,l3);
    long o = (long)i * QKVW + m * DD + h * HD + d;
    *(uint32_t*)(dh + o    ) = packb(h0,h1);
    *(uint32_t*)(dh + o + 2) = packb(h2,h3);
    *(uint32_t*)(dl + o    ) = packb(l0,l1);
    *(uint32_t*)(dl + o + 2) = packb(l2,l3);
}

__global__ void pack_qkv_b(const float* __restrict__ bq,
                           const float* __restrict__ bk,
                           const float* __restrict__ bv,
                           float* __restrict__ bp)
{
    int idx = blockIdx.x * blockDim.x + threadIdx.x;
    if (idx >= QKVW) return;
    int m = idx / DD;
    int r = idx % DD;
    const float* src = (m == 0) ? bq : (m == 1) ? bk : bv;
    bp[idx] = src[r] * ((m == 0) ? FSC : 1.0f);
}

// ---------------- V column sums ----------------
__global__ void vsum_kernel(const __nv_bfloat16* __restrict__ qkvh,
                            float* __restrict__ vsum)
{
    int z = blockIdx.x;
    int d = threadIdx.x & 63;
    int rg = threadIdx.x >> 6;
    const __nv_bfloat16* v = qkvh + (long)(z >> 3) * SS * QKVW + (z & 7) * HD + 2 * DD;
    float s = 0.f;
    for (int j = rg; j < SS; j += 4)
        s += __bfloat162float(v[(long)j * QKVW + d]);
    __shared__ float red[256];
    red[threadIdx.x] = s;
    __syncthreads();
    if (rg == 0)
        vsum[z * HD + d] = red[d] + red[64 + d] + red[128 + d] + red[192 + d];
}

// ---------------- split-K combine epilogues ----------------
__global__ void up_pack(const float* __restrict__ scr,
                        const float* __restrict__ bt,
                        __nv_bfloat16* __restrict__ uh,
                        __nv_bfloat16* __restrict__ ul)
{
    int i = blockIdx.x * blockDim.x + threadIdx.x;
    if (i >= BB * PP * DD / 4) return;
    int e = i * 4;
    float bias = bt[(e / DD) % PP];
    float4 a = ((const float4*)scr)[i];
    float4 b = ((const float4*)(scr + (size_t)BB * PP * DD))[i];
    float v0 = a.x + b.x + bias, v1 = a.y + b.y + bias;
    float v2 = a.z + b.z + bias, v3 = a.w + b.w + bias;
    __nv_bfloat16 h0,l0,h1,l1,h2,l2,h3,l3;
    split_bf16(v0,h0,l0); split_bf16(v1,h1,l1);
    split_bf16(v2,h2,l2); split_bf16(v3,h3,l3);
    ((uint32_t*)uh)[2*i  ] = packb(h0,h1);
    ((uint32_t*)uh)[2*i+1] = packb(h2,h3);
    ((uint32_t*)ul)[2*i  ] = packb(l0,l1);
    ((uint32_t*)ul)[2*i+1] = packb(l2,l3);
}

__global__ void out_final(const float* __restrict__ scr,
                          const float* __restrict__ bo,
                          float* __restrict__ out)
{
    int i = blockIdx.x * blockDim.x + threadIdx.x;
    if (i >= BB * PP * II / 4) return;
    int e = i * 4;
    float4 bb = *(const float4*)(bo + (e % II));
    float4 a = ((const float4*)scr)[i];
    float4 b = ((const float4*)(scr + (size_t)BB * PP * II))[i];
    float4 r;
    r.x = a.x + b.x + bb.x; r.y = a.y + b.y + bb.y;
    r.z = a.z + b.z + bb.z; r.w = a.w + b.w + bb.w;
    ((float4*)out)[i] = r;
}

// ---------------- bf16-plane tensor-core GEMM ----------------
#define GBM 128
#define GBN 64
#define GBK 32
#define ASTR 40
#define BSTR 72
#define A_TILE (GBM*ASTR)
#define B_TILE (GBN*ASTR)
#define STAGE (2*A_TILE + 2*B_TILE)
#define GSMEM (2*STAGE*2)

__device__ __forceinline__ void gemm_load_stage(
    __nv_bfloat16* buf,
    const __nv_bfloat16* __restrict__ Ah, const __nv_bfloat16* __restrict__ Al,
    long a_off, int lda, int M, int m0,
    const __nv_bfloat16* __restrict__ Bh, const __nv_bfloat16* __restrict__ Bl,
    long b_off, int ldb, int n0, int k0, int tid, int three_term, int b_kmajor)
{
    #pragma unroll
    for (int i = 0; i < 4; i++) {
        int e = tid + i * 256;
        int plane = e >> 9;
        if (plane && !three_term) continue;
        int rem = e & 511;
        int m = rem >> 2;
        int seg = rem & 3;
        int mg = m0 + m; if (mg >= M) mg = M - 1;
        const __nv_bfloat16* src = (plane ? Al : Ah) + a_off + (long)mg * lda + k0 + seg * 8;
        cp16(buf + plane * A_TILE + m * ASTR + seg * 8, src);
    }
    if (b_kmajor) {
        #pragma unroll
        for (int i = 0; i < 2; i++) {
            int e = tid + i * 256;
            int plane = e >> 8;
            if (plane && !three_term) continue;
            int rem = e & 255;
            int n = rem >> 2;
            int seg = rem & 3;
            const __nv_bfloat16* src = (plane ? Bl : Bh) + b_off + (long)(n0 + n) * ldb + k0 + seg * 8;
            cp16(buf + 2 * A_TILE + plane * B_TILE + n * ASTR + seg * 8, src);
        }
    } else {
        #pragma unroll
        for (int i = 0; i < 2; i++) {
            int e = tid + i * 256;
            int plane = e >> 8;
            if (plane && !three_term) continue;
            int rem = e & 255;
            int k = rem >> 3;
            int seg = rem & 7;
            const __nv_bfloat16* src = (plane ? Bl : Bh) + b_off + (long)(k0 + k) * ldb + n0 + seg * 8;
            cp16(buf + 2 * A_TILE + plane * B_TILE + k * BSTR + seg * 8, src);
        }
    }
}

__global__ __launch_bounds__(256, 2)
void gemm_planes(
    int M, int N, int K,
    const __nv_bfloat16* __restrict__ Ah, const __nv_bfloat16* __restrict__ Al,
    long a_bo, long a_bi, int lda,
    const __nv_bfloat16* __restrict__ Bh, const __nv_bfloat16* __restrict__ Bl,
    long b_bo, long b_bi, int ldb,
    float* __restrict__ C, __nv_bfloat16* __restrict__ Ch, __nv_bfloat16* __restrict__ Cl,
    long c_bo, long c_bi, int ldc,
    const float* __restrict__ bias, int bias_mode, int three_term, int b_kmajor,
    int z_inner)
{
    extern __shared__ __align__(16) __nv_bfloat16 gsm[];
    const int z  = blockIdx.z;
    const int zo = z / z_inner;
    const int zi = z % z_inner;
    const long a_off = (long)zo * a_bo + (long)zi * a_bi;
    const long b_off = (long)zo * b_bo + (long)zi * b_bi;
    const long c_off = (long)zo * c_bo + (long)zi * c_bi;
    const int m0 = blockIdx.y * GBM;
    const int n0 = blockIdx.x * GBN;
    const int tt = (three_term == 2) ? ((n0 >= 2 * DD) ? 1 : 0) : three_term;

    const int tid  = threadIdx.x;
    const int lane = tid & 31;
    const int warp = tid >> 5;
    const int wm = (warp & 3) * 32;
    const int wn = (warp >> 2) * 32;
    const int qr = lane >> 2;
    const int qc = (lane & 3) * 2;
    const int a_row = ((lane >> 3) & 1) * 8 + (lane & 7);
    const int a_col = (lane >> 4) * 8;
    const int b_row = ((lane >> 3) & 1) * 8 + (lane & 7);
    const int b_col = ((lane >> 4) & 1) * 8;
    const int bk_row = ((lane >> 4) & 1) * 8 + (lane & 7);
    const int bk_col = ((lane >> 3) & 1) * 8;

    float acc[2][4][4] = {};

    gemm_load_stage(gsm, Ah, Al, a_off, lda, M, m0, Bh, Bl, b_off, ldb, n0, 0, tid, tt, b_kmajor);
    CP_COMMIT();

    const int nstage = K / GBK;
    for (int s = 0; s < nstage; s++) {
        CP_WAIT0();
        __syncthreads();
        if (s + 1 < nstage) {
            gemm_load_stage(gsm + ((s + 1) & 1) * STAGE,
                            Ah, Al, a_off, lda, M, m0,
                            Bh, Bl, b_off, ldb, n0, (s + 1) * GBK, tid, tt, b_kmajor);
            CP_COMMIT();
        }
        const __nv_bfloat16* As = gsm + (s & 1) * STAGE;
        const __nv_bfloat16* Bs = As + 2 * A_TILE;

        #pragma unroll
        for (int ks = 0; ks < 2; ks++) {
            const int kc = ks * 16;
            uint32_t ah[2][4], al[2][4], bh[2][4], bl[2][4];
            #pragma unroll
            for (int mt = 0; mt < 2; mt++) {
                const __nv_bfloat16* base = As + (wm + mt * 16 + a_row) * ASTR + kc + a_col;
                ldsm4(ah[mt], base);
                if (tt) ldsm4(al[mt], base + A_TILE);
            }
            if (b_kmajor) {
                #pragma unroll
                for (int ng = 0; ng < 2; ng++) {
                    const __nv_bfloat16* base = Bs + (wn + ng * 16 + bk_row) * ASTR + kc + bk_col;
                    ldsm4(bh[ng], base);
                    if (tt) ldsm4(bl[ng], base + B_TILE);
                }
            } else {
                #pragma unroll
                for (int ng = 0; ng < 2; ng++) {
                    const __nv_bfloat16* base = Bs + (kc + b_row) * BSTR + wn + ng * 16 + b_col;
                    ldsm4t(bh[ng], base);
                    if (tt) ldsm4t(bl[ng], base + B_TILE);
                }
            }
            #pragma unroll
            for (int mt = 0; mt < 2; mt++)
                #pragma unroll
                for (int ng = 0; ng < 2; ng++) {
                    mma_bf16(acc[mt][2 * ng    ], ah[mt], bh[ng]);
                    mma_bf16(acc[mt][2 * ng + 1], ah[mt], bh[ng] + 2);
                    if (tt) {
                        mma_bf16(acc[mt][2 * ng    ], al[mt], bh[ng]);
                        mma_bf16(acc[mt][2 * ng    ], ah[mt], bl[ng]);
                        mma_bf16(acc[mt][2 * ng + 1], al[mt], bh[ng] + 2);
                        mma_bf16(acc[mt][2 * ng + 1], ah[mt], bl[ng] + 2);
                    }
                }
        }
    }

    // --- epilogue
    #pragma unroll
    for (int mt = 0; mt < 2; mt++) {
        #pragma unroll
        for (int nt = 0; nt < 4; nt++) {
            int r0 = m0 + wm + mt * 16 + qr;
            int r1 = r0 + 8;
            int c  = n0 + wn + nt * 8 + qc;
            float bn0 = 0.f, bn1 = 0.f;
            if (bias_mode == 1) { bn0 = bias[c]; bn1 = bias[c + 1]; }
            float v00 = acc[mt][nt][0] + bn0;
            float v01 = acc[mt][nt][1] + bn1;
            float v10 = acc[mt][nt][2] + bn0;
            float v11 = acc[mt][nt][3] + bn1;
            if (bias_mode == 2) {
                if (r0 < M) { float bm = bias[r0]; v00 += bm; v01 += bm; }
                if (r1 < M) { float bm = bias[r1]; v10 += bm; v11 += bm; }
            }
            if (Ch && Cl) {
                __nv_bfloat16 h0, l0, h1, l1;
                if (r0 < M) {
                    split_bf16(v00, h0, l0); split_bf16(v01, h1, l1);
                    *(uint32_t*)(Ch + c_off + (long)r0 * ldc + c) = packb(h0, h1);
                    *(uint32_t*)(Cl + c_off + (long)r0 * ldc + c) = packb(l0, l1);
                }
                if (r1 < M) {
                    split_bf16(v10, h0, l0); split_bf16(v11, h1, l1);
                    *(uint32_t*)(Ch + c_off + (long)r1 * ldc + c) = packb(h0, h1);
                    *(uint32_t*)(Cl + c_off + (long)r1 * ldc + c) = packb(l0, l1);
                }
            } else if (Ch) {
                if (r0 < M)
                    *(uint32_t*)(Ch + c_off + (long)r0 * ldc + c) = cvt_bf16x2(v00, v01);
                if (r1 < M)
                    *(uint32_t*)(Ch + c_off + (long)r1 * ldc + c) = cvt_bf16x2(v10, v11);
            } else {
                if (r0 < M) {
                    C[c_off + (long)r0 * ldc + c    ] = v00;
                    C[c_off + (long)r0 * ldc + c + 1] = v01;
                }
                if (r1 < M) {
                    C[c_off + (long)r1 * ldc + c    ] = v10;
                    C[c_off + (long)r1 * ldc + c + 1] = v11;
                }
            }
        }
    }
}

// ---------------- fused flash attention ----------------
// Q pre-scaled by 1/64 at pack time; softmax via packed f32x2 expm1.
#define VKP 72
#define FTILE (64*VKP)
#define NTILES 2
#define NSTAGE 3
#define FSMEM (NSTAGE*NTILES*FTILE*2)

__device__ __forceinline__ void flash_load_chunk(
    __nv_bfloat16* buf,
    const __nv_bfloat16* __restrict__ qh_plane,
    long kbase, long vbase, int c, int tid)
{
    #pragma unroll
    for (int i = 0; i < 8; i++) {
        int e    = tid + i * 128;
        int tile = e >> 9;
        int rem  = e & 511;
        int row  = rem >> 3;
        int seg  = rem & 7;
        long off = ((tile == 0) ? kbase : vbase) + (long)(c * 64 + row) * QKVW + seg * 8;
        cp16(buf + tile * FTILE + row * VKP + seg * 8, qh_plane + off);
    }
}

__global__ __launch_bounds__(128, 4)
void flash_attn(const __nv_bfloat16* __restrict__ qh_plane,
                const float* __restrict__ vsum,
                __nv_bfloat16* __restrict__ combh,
                __nv_bfloat16* __restrict__ combl)
{
    extern __shared__ __align__(16) __nv_bfloat16 sm[];
    const int z = blockIdx.y;
    const int b = z >> 3, h = z & 7;
    const int m0 = blockIdx.x * 64;
    const int tid  = threadIdx.x;
    const int lane = tid & 31;
    const int warp = tid >> 5;
    const int qr = lane >> 2;
    const int qc = (lane & 3) * 2;

    const long zbase = (long)b * SS * QKVW + h * HD;
    const long kbase = zbase + DD;
    const long vbase = zbase + 2 * DD;

    const int r0 = m0 + warp * 16 + qr;
    uint32_t qh[4][4];
    #pragma unroll
    for (int ks = 0; ks < 4; ks++) {
        #pragma unroll
        for (int a = 0; a < 4; a++) {
            int row = r0 + (a & 1) * 8;
            int col = ks * 16 + qc + (a >> 1) * 8;
            qh[ks][a] = *(const uint32_t*)(qh_plane + zbase + (long)row * QKVW + col);
        }
    }

    float o[8][4] = {};
    uint64_t L01 = pk2(0.f, 0.f), L23 = pk2(0.f, 0.f);  // packed row-sum accumulators

    const int skey_off = ((lane >> 4) & 1) * 8 + (lane & 7);
    const int scol_off = ((lane >> 3) & 1) * 8;
    const int vkey_off = ((lane >> 3) & 1) * 8 + (lane & 7);
    const int vcol_off = ((lane >> 4) & 1) * 8;

    flash_load_chunk(sm, qh_plane, kbase, vbase, 0, tid);
    CP_COMMIT();
    flash_load_chunk(sm + NTILES * FTILE, qh_plane, kbase, vbase, 1, tid);
    CP_COMMIT();

    int buf_c = 0;
    for (int c = 0; c < SS / 64; c++) {
        CP_WAIT1();
        __syncthreads();
        const __nv_bfloat16* Kh_ = sm + buf_c * NTILES * FTILE;
        const __nv_bfloat16* Vh_ = Kh_ + FTILE;

        if (c + 2 < SS / 64) {
            int buf_n = buf_c + 2; if (buf_n >= NSTAGE) buf_n -= NSTAGE;
            flash_load_chunk(sm + buf_n * NTILES * FTILE,
                             qh_plane, kbase, vbase, c + 2, tid);
        }
        CP_COMMIT();

        // --- S = Q K^T (1-term; pre-scaled)
        float s[8][4] = {};
        #pragma unroll
        for (int ks = 0; ks < 4; ks++) {
            const int kc = ks * 16;
            #pragma unroll
            for (int ntp = 0; ntp < 4; ntp++) {
                const __nv_bfloat16* base = Kh_ + (ntp * 16 + skey_off) * VKP + kc + scol_off;
                uint32_t bh[4];
                ldsm4(bh, base);
                mma_bf16(s[2 * ntp    ], qh[ks], bh);
                mma_bf16(s[2 * ntp + 1], qh[ks], bh + 2);
            }
        }

        // --- t = expm1(s) via packed f32x2 poly; packed sum accumulation
        uint32_t ph[4][4];
        #pragma unroll
        for (int nt = 0; nt < 8; nt++) {
            uint64_t x01 = pk2(s[nt][0], s[nt][1]);
            uint64_t x23 = pk2(s[nt][2], s[nt][3]);
            uint64_t t01 = expm1_poly2(x01);
            uint64_t t23 = expm1_poly2(x23);
            L01 = add2(L01, t01);
            L23 = add2(L23, t23);
            int ks = nt >> 1, off = (nt & 1) * 2;
            ph[ks][off    ] = cvt_bf16x2_p(t01);
            ph[ks][off + 1] = cvt_bf16x2_p(t23);
        }

        // --- O += T V (1-term)
        #pragma unroll
        for (int ks = 0; ks < 4; ks++) {
            const int kc = ks * 16;
            #pragma unroll
            for (int ntp = 0; ntp < 4; ntp++) {
                const __nv_bfloat16* base = Vh_ + (kc + vkey_off) * VKP + ntp * 16 + vcol_off;
                uint32_t vh4[4];
                ldsm4t(vh4, base);
                mma_bf16(o[2 * ntp    ], ph[ks], vh4);
                mma_bf16(o[2 * ntp + 1], ph[ks], vh4 + 2);
            }
        }
        if (++buf_c >= NSTAGE) buf_c = 0;
    }

    // --- horizontal reduce packed sums, quad shuffles, normalize, write
    float a0, a1, b0, b1;
    unpk2(L01, a0, a1);
    unpk2(L23, b0, b1);
    float l0r = a0 + a1, l1r = b0 + b1;
    l0r += __shfl_xor_sync(0xffffffff, l0r, 1);
    l0r += __shfl_xor_sync(0xffffffff, l0r, 2);
    l1r += __shfl_xor_sync(0xffffffff, l1r, 1);
    l1r += __shfl_xor_sync(0xffffffff, l1r, 2);
    float inv0 = 1.f / (l0r + (float)SS), inv1 = 1.f / (l1r + (float)SS);
    const float* vs = vsum + z * HD;
    const long cbase = (long)b * SS * DD + h * HD;
    #pragma unroll
    for (int nt = 0; nt < 8; nt++) {
        int col = nt * 8 + qc;
        float vs0 = vs[col], vs1 = vs[col + 1];
        __nv_bfloat16 h0, l0, h1, l1;
        split_bf16((o[nt][0] + vs0) * inv0, h0, l0);
        split_bf16((o[nt][1] + vs1) * inv0, h1, l1);
        *(uint32_t*)(combh + cbase + (long)r0 * DD + col) = packb(h0, h1);
        *(uint32_t*)(combl + cbase + (long)r0 * DD + col) = packb(l0, l1);
        split_bf16((o[nt][2] + vs0) * inv1, h0, l0);
        split_bf16((o[nt][3] + vs1) * inv1, h1, l1);
        *(uint32_t*)(combh + cbase + (long)(r0 + 8) * DD + col) = packb(h0, h1);
        *(uint32_t*)(combl + cbase + (long)(r0 + 8) * DD + col) = packb(l0, l1);
    }
}

// ---------------- launch ----------------
extern "C" void kernel_launch(void* const* d_in, const int* in_sizes, int n_in,
                              void* d_out, int out_size)
{
    (void)in_sizes; (void)n_in; (void)out_size;
    const float* x  = (const float*)d_in[0];
    const float* Wq = (const float*)d_in[1];
    const float* bq = (const float*)d_in[2];
    const float* Wk = (const float*)d_in[3];
    const float* bk = (const float*)d_in[4];
    const float* Wv = (const float*)d_in[5];
    const float* bv = (const float*)d_in[6];
    const float* Wt = (const float*)d_in[7];
    const float* bt = (const float*)d_in[8];
    const float* Wo = (const float*)d_in[9];
    const float* bo = (const float*)d_in[10];
    float* out = (float*)d_out;

    __nv_bfloat16 *qkvh, *combh, *combl, *uph, *upl;
    __nv_bfloat16 *xh, *xl, *wph, *wpl, *wth, *wtl, *woh, *wol;
    float *bp, *vsum, *scr;
    cudaGetSymbolAddress((void**)&qkvh,  g_qkvh);
    cudaGetSymbolAddress((void**)&combh, g_combh);
    cudaGetSymbolAddress((void**)&combl, g_combl);
    cudaGetSymbolAddress((void**)&uph,   g_uph);
    cudaGetSymbolAddress((void**)&upl,   g_upl);
    cudaGetSymbolAddress((void**)&xh,    g_xh);
    cudaGetSymbolAddress((void**)&xl,    g_xl);
    cudaGetSymbolAddress((void**)&wph,   g_wph);
    cudaGetSymbolAddress((void**)&wpl,   g_wpl);
    cudaGetSymbolAddress((void**)&wth,   g_wth);
    cudaGetSymbolAddress((void**)&wtl,   g_wtl);
    cudaGetSymbolAddress((void**)&woh,   g_woh);
    cudaGetSymbolAddress((void**)&wol,   g_wol);
    cudaGetSymbolAddress((void**)&bp,    g_bp);
    cudaGetSymbolAddress((void**)&vsum,  g_vsum);
    cudaGetSymbolAddress((void**)&scr,   g_scr);

    static cudaStream_t s2 = nullptr;
    static cudaEvent_t evF = nullptr, evJ = nullptr;
    static bool attr_set = false;
    if (!attr_set) {
        cudaFuncSetAttribute(flash_attn,
            cudaFuncAttributeMaxDynamicSharedMemorySize, FSMEM);
        cudaFuncSetAttribute(gemm_planes,
            cudaFuncAttributeMaxDynamicSharedMemorySize, GSMEM);
        cudaStreamCreateWithFlags(&s2, cudaStreamNonBlocking);
        cudaEventCreateWithFlags(&evF, cudaEventDisableTiming);
        cudaEventCreateWithFlags(&evJ, cudaEventDisableTiming);
        attr_set = true;
    }

    // fork: Wt/Wo packs on side stream
    cudaEventRecord(evF, 0);
    cudaStreamWaitEvent(s2, evF, 0);
    pack_split4<<<(PP * SS / 4 + 255) / 256, 256, 0, s2>>>(Wt, wth, wtl, PP * SS / 4);
    pack_split4<<<(II * DD / 4 + 255) / 256, 256, 0, s2>>>(Wo, woh, wol, II * DD / 4);
    cudaEventRecord(evJ, s2);

    // main stream: x / QKV-weight packs
    pack_split4<<<(NT * II / 4 + 255) / 256, 256>>>(x, xh, xl, NT * II / 4);
    pack_qkv_w<<<(3 * II * DD / 4 + 255) / 256, 256>>>(Wq, Wk, Wv, wph, wpl);
    pack_qkv_b<<<(QKVW + 255) / 256, 256>>>(bq, bk, bv, bp);

    // 1) merged QKV projection -> qkvh (hi-only); QK 1-term, V 3-term (auto)
    {
        dim3 grid(QKVW / GBN, NT / GBM, 1);
        gemm_planes<<<grid, 256, GSMEM>>>(NT, QKVW, II,
            xh, xl, 0, 0, II,
            wph, wpl, 0, 0, QKVW,
            nullptr, qkvh, nullptr, 0, 0, QKVW,
            bp, 1, 2, 0, 1);
    }

    // 1c) V column sums per (b,h)
    vsum_kernel<<<BB * HH, 256>>>(qkvh, vsum);

    // 2) fused attention -> comb planes [B,S,D]
    {
        dim3 grid(SS / 64, BB * HH);
        flash_attn<<<grid, 128, FSMEM>>>(qkvh, vsum, combh, combl);
    }

    // join: Wt/Wo packs must be done before tail GEMMs
    cudaStreamWaitEvent(0, evJ, 0);

    // 3) temporal (3-term), split-K=2 -> fp32 scratch partials
    {
        dim3 grid(DD / GBN, (PP + GBM - 1) / GBM, BB * 2);
        gemm_planes<<<grid, 256, GSMEM>>>(PP, DD, SS / 2,
            wth, wtl, 0, SS / 2, SS,
            combh, combl, (long)SS * DD, (long)(SS / 2) * DD, DD,
            scr, nullptr, nullptr, (long)PP * DD, (long)BB * PP * DD, DD,
            nullptr, 0, 1, 0, 2);
    }
    up_pack<<<(BB * PP * DD / 4 + 255) / 256, 256>>>(scr, bt, uph, upl);

    // 4) out (3-term, B k-major), split-K=2 -> fp32 scratch partials
    {
        dim3 grid(II / GBN, (PP + GBM - 1) / GBM, BB * 2);
        gemm_planes<<<grid, 256, GSMEM>>>(PP, II, DD / 2,
            uph, upl, (long)PP * DD, DD / 2, DD,
            woh, wol, 0, DD / 2, DD,
            scr, nullptr, nullptr, (long)PP * II, (long)BB * PP * II, II,
            nullptr, 0, 1, 1, 2);
    }
    out_final<<<(BB * PP * II / 4 + 255) / 256, 256>>>(scr, bo, out);
}

// round 17
// speedup vs baseline: 1.1660x; 1.0994x over previous
#include <cuda_runtime.h>
#include <cuda_bf16.h>
#include <math.h>
#include <stdint.h>

// Problem dims
#define BB 4
#define SS 2048
#define II 512
#define DD 512
#define HH 8
#define HD 64
#define PP 720
#define NT (BB*SS)        // 8192 tokens
#define QKVW (3*DD)       // 1536
#define FSC 0.015625f     // 1/HD (power of two -> exact fold into Wq/bq)

// ---------------- scratch (__device__ globals, no allocation) ----------------
__device__ __nv_bfloat16 g_qkvh[(size_t)NT * QKVW];
__device__ __nv_bfloat16 g_combh[(size_t)NT * DD];
__device__ __nv_bfloat16 g_combl[(size_t)NT * DD];
__device__ __nv_bfloat16 g_uph[(size_t)BB * PP * DD];
__device__ __nv_bfloat16 g_upl[(size_t)BB * PP * DD];
__device__ __nv_bfloat16 g_xh[(size_t)NT * II];
__device__ __nv_bfloat16 g_wph[(size_t)II * QKVW];
__device__ __nv_bfloat16 g_wth[(size_t)PP * SS];
__device__ __nv_bfloat16 g_wtl[(size_t)PP * SS];
__device__ __nv_bfloat16 g_woh[(size_t)II * DD];   // natural [o][d] layout
__device__ __nv_bfloat16 g_wol[(size_t)II * DD];
__device__ float g_bp[QKVW];
__device__ float g_vsum[BB * HH * HD];
__device__ float g_xpart[BB * 8 * II];             // token-sum partials of x
__device__ float g_scr[2 * (size_t)BB * PP * DD];  // split-K partials

// ---------------- helpers ----------------
__device__ __forceinline__ void mma_bf16(float* c, const uint32_t* a, const uint32_t* b) {
    asm volatile(
        "mma.sync.aligned.m16n8k16.row.col.f32.bf16.bf16.f32 "
        "{%0,%1,%2,%3}, {%4,%5,%6,%7}, {%8,%9}, {%0,%1,%2,%3};\n"
        : "+f"(c[0]), "+f"(c[1]), "+f"(c[2]), "+f"(c[3])
        : "r"(a[0]), "r"(a[1]), "r"(a[2]), "r"(a[3]), "r"(b[0]), "r"(b[1]));
}
__device__ __forceinline__ void split_bf16(float x, __nv_bfloat16& h, __nv_bfloat16& l) {
    h = __float2bfloat16(x);
    l = __float2bfloat16(x - __bfloat162float(h));
}
__device__ __forceinline__ uint32_t packb(__nv_bfloat16 a, __nv_bfloat16 b) {
    __nv_bfloat162 t; t.x = a; t.y = b;
    return *(uint32_t*)&t;
}
__device__ __forceinline__ uint32_t cvt_bf16x2(float lo, float hi) {
    uint32_t r;
    asm("cvt.rn.bf16x2.f32 %0, %1, %2;" : "=r"(r) : "f"(hi), "f"(lo));
    return r;
}
// ---- packed f32x2 ----
__device__ __forceinline__ uint64_t pk2(float lo, float hi) {
    uint64_t r;
    asm("mov.b64 %0, {%1, %2};" : "=l"(r) : "f"(lo), "f"(hi));
    return r;
}
__device__ __forceinline__ void unpk2(uint64_t v, float& lo, float& hi) {
    asm("mov.b64 {%0, %1}, %2;" : "=f"(lo), "=f"(hi) : "l"(v));
}
__device__ __forceinline__ uint64_t fma2(uint64_t a, uint64_t b, uint64_t c) {
    uint64_t r;
    asm("fma.rn.f32x2 %0, %1, %2, %3;" : "=l"(r) : "l"(a), "l"(b), "l"(c));
    return r;
}
__device__ __forceinline__ uint64_t mul2(uint64_t a, uint64_t b) {
    uint64_t r;
    asm("mul.rn.f32x2 %0, %1, %2;" : "=l"(r) : "l"(a), "l"(b));
    return r;
}
__device__ __forceinline__ uint64_t add2(uint64_t a, uint64_t b) {
    uint64_t r;
    asm("add.rn.f32x2 %0, %1, %2;" : "=l"(r) : "l"(a), "l"(b));
    return r;
}
__device__ __forceinline__ uint32_t cvt_bf16x2_p(uint64_t p) {
    uint32_t r;
    asm("{\n\t.reg .f32 lo, hi;\n\tmov.b64 {lo, hi}, %1;\n\t"
        "cvt.rn.bf16x2.f32 %0, hi, lo;\n\t}" : "=r"(r) : "l"(p));
    return r;
}
__device__ __forceinline__ uint64_t expm1_poly2(uint64_t x) {
    const uint64_t C16 = pk2(0.16666667f, 0.16666667f);
    const uint64_t C05 = pk2(0.5f, 0.5f);
    const uint64_t C1  = pk2(1.0f, 1.0f);
    uint64_t i1 = fma2(x, C16, C05);
    uint64_t i2 = fma2(x, i1, C1);
    return mul2(x, i2);
}
__device__ __forceinline__ void ldsm4(uint32_t* r, const __nv_bfloat16* p) {
    uint32_t a = (uint32_t)__cvta_generic_to_shared(p);
    asm volatile("ldmatrix.sync.aligned.m8n8.x4.shared.b16 {%0,%1,%2,%3}, [%4];\n"
        : "=r"(r[0]), "=r"(r[1]), "=r"(r[2]), "=r"(r[3]) : "r"(a));
}
__device__ __forceinline__ void ldsm4t(uint32_t* r, const __nv_bfloat16* p) {
    uint32_t a = (uint32_t)__cvta_generic_to_shared(p);
    asm volatile("ldmatrix.sync.aligned.m8n8.x4.trans.shared.b16 {%0,%1,%2,%3}, [%4];\n"
        : "=r"(r[0]), "=r"(r[1]), "=r"(r[2]), "=r"(r[3]) : "r"(a));
}
__device__ __forceinline__ void cp16(__nv_bfloat16* dst, const __nv_bfloat16* src) {
    uint32_t d = (uint32_t)__cvta_generic_to_shared(dst);
    asm volatile("cp.async.cg.shared.global [%0], [%1], 16;\n" :: "r"(d), "l"(src));
}
#define CP_COMMIT() asm volatile("cp.async.commit_group;\n")
#define CP_WAIT0()  asm volatile("cp.async.wait_group 0;\n")
#define CP_WAIT1()  asm volatile("cp.async.wait_group 1;\n")

// ---------------- pack kernels ----------------
__global__ void pack_split4(const float* __restrict__ src,
                            __nv_bfloat16* __restrict__ dh,
                            __nv_bfloat16* __restrict__ dl, int n4)
{
    int i = blockIdx.x * blockDim.x + threadIdx.x;
    if (i >= n4) return;
    float4 v = ((const float4*)src)[i];
    __nv_bfloat16 h0,l0,h1,l1,h2,l2,h3,l3;
    split_bf16(v.x,h0,l0); split_bf16(v.y,h1,l1);
    split_bf16(v.z,h2,l2); split_bf16(v.w,h3,l3);
    ((uint32_t*)dh)[2*i  ] = packb(h0,h1);
    ((uint32_t*)dh)[2*i+1] = packb(h2,h3);
    ((uint32_t*)dl)[2*i  ] = packb(l0,l1);
    ((uint32_t*)dl)[2*i+1] = packb(l2,l3);
}

// hi-only pack (x)
__global__ void pack_split4_h(const float* __restrict__ src,
                              __nv_bfloat16* __restrict__ dh, int n4)
{
    int i = blockIdx.x * blockDim.x + threadIdx.x;
    if (i >= n4) return;
    float4 v = ((const float4*)src)[i];
    ((uint32_t*)dh)[2*i  ] = cvt_bf16x2(v.x, v.y);
    ((uint32_t*)dh)[2*i+1] = cvt_bf16x2(v.z, v.w);
}

// Wq scaled by FSC at pack time (power-of-two: exact); hi-only output
__global__ void pack_qkv_w(const float* __restrict__ Wq,
                           const float* __restrict__ Wk,
                           const float* __restrict__ Wv,
                           __nv_bfloat16* __restrict__ dh)
{
    int idx = blockIdx.x * blockDim.x + threadIdx.x;   // over 3*512*512/4
    if (idx >= 3 * II * DD / 4) return;
    int e   = idx * 4;
    int m   = e / (II * DD);
    int rem = e % (II * DD);            // = h*(512*64) + i*64 + d
    int h   = rem / (II * HD);
    int i   = (rem / HD) % II;
    int d   = rem % HD;
    const float* src = (m == 0) ? Wq : (m == 1) ? Wk : Wv;
    float sc = (m == 0) ? FSC : 1.0f;
    float4 v = *(const float4*)(src + rem);
    long o = (long)i * QKVW + m * DD + h * HD + d;
    *(uint32_t*)(dh + o    ) = cvt_bf16x2(v.x * sc, v.y * sc);
    *(uint32_t*)(dh + o + 2) = cvt_bf16x2(v.z * sc, v.w * sc);
}

__global__ void pack_qkv_b(const float* __restrict__ bq,
                           const float* __restrict__ bk,
                           const float* __restrict__ bv,
                           float* __restrict__ bp)
{
    int idx = blockIdx.x * blockDim.x + threadIdx.x;
    if (idx >= QKVW) return;
    int m = idx / DD;
    int r = idx % DD;
    const float* src = (m == 0) ? bq : (m == 1) ? bk : bv;
    bp[idx] = src[r] * ((m == 0) ? FSC : 1.0f);
}

// ---------------- exact V column sums from x and Wv (fp32) ----------------
// xpart[b*8+seg][i] = sum over 256 tokens of x[b, seg*256+.., i]
__global__ void xsum_part(const float* __restrict__ x, float* __restrict__ xpart)
{
    int b = blockIdx.x >> 3, seg = blockIdx.x & 7;
    int tid = threadIdx.x;  // 256
    #pragma unroll
    for (int ib = 0; ib < 2; ib++) {
        int i = ib * 256 + tid;
        float s = 0.f;
        const float* p = x + ((long)b * SS + seg * 256) * II + i;
        for (int ss = 0; ss < 256; ss++)
            s += p[(long)ss * II];
        xpart[blockIdx.x * II + i] = s;
    }
}

// vsum[z=b*8+h][d] = sum_i xsum[b][i]*Wv[h,i,d] + S*bv[h,d]   (exact fp32)
__global__ void vsum2_kernel(const float* __restrict__ xpart,
                             const float* __restrict__ Wv,
                             const float* __restrict__ bv,
                             float* __restrict__ vsum)
{
    int z = blockIdx.x;
    int b = z >> 3, h = z & 7;
    int tid = threadIdx.x;  // 256
    __shared__ float xs[II];
    #pragma unroll
    for (int ib = 0; ib < 2; ib++) {
        int i = ib * 256 + tid;
        float s = 0.f;
        #pragma unroll
        for (int seg = 0; seg < 8; seg++)
            s += xpart[(b * 8 + seg) * II + i];
        xs[i] = s;
    }
    __syncthreads();
    int d = tid & 63, rg = tid >> 6;
    float acc = 0.f;
    const float* wv = Wv + (long)h * II * HD + d;
    for (int i = rg * 128; i < rg * 128 + 128; i++)
        acc += xs[i] * wv[(long)i * HD];
    __shared__ float red[256];
    red[tid] = acc;
    __syncthreads();
    if (rg == 0)
        vsum[z * HD + d] = red[d] + red[64 + d] + red[128 + d] + red[192 + d]
                         + (float)SS * bv[h * HD + d];
}

// ---------------- split-K combine epilogues ----------------
__global__ void up_pack(const float* __restrict__ scr,
                        const float* __restrict__ bt,
                        __nv_bfloat16* __restrict__ uh,
                        __nv_bfloat16* __restrict__ ul)
{
    int i = blockIdx.x * blockDim.x + threadIdx.x;
    if (i >= BB * PP * DD / 4) return;
    int e = i * 4;
    float bias = bt[(e / DD) % PP];
    float4 a = ((const float4*)scr)[i];
    float4 b = ((const float4*)(scr + (size_t)BB * PP * DD))[i];
    float v0 = a.x + b.x + bias, v1 = a.y + b.y + bias;
    float v2 = a.z + b.z + bias, v3 = a.w + b.w + bias;
    __nv_bfloat16 h0,l0,h1,l1,h2,l2,h3,l3;
    split_bf16(v0,h0,l0); split_bf16(v1,h1,l1);
    split_bf16(v2,h2,l2); split_bf16(v3,h3,l3);
    ((uint32_t*)uh)[2*i  ] = packb(h0,h1);
    ((uint32_t*)uh)[2*i+1] = packb(h2,h3);
    ((uint32_t*)ul)[2*i  ] = packb(l0,l1);
    ((uint32_t*)ul)[2*i+1] = packb(l2,l3);
}

__global__ void out_final(const float* __restrict__ scr,
                          const float* __restrict__ bo,
                          float* __restrict__ out)
{
    int i = blockIdx.x * blockDim.x + threadIdx.x;
    if (i >= BB * PP * II / 4) return;
    int e = i * 4;
    float4 bb = *(const float4*)(bo + (e % II));
    float4 a = ((const float4*)scr)[i];
    float4 b = ((const float4*)(scr + (size_t)BB * PP * II))[i];
    float4 r;
    r.x = a.x + b.x + bb.x; r.y = a.y + b.y + bb.y;
    r.z = a.z + b.z + bb.z; r.w = a.w + b.w + bb.w;
    ((float4*)out)[i] = r;
}

// ---------------- bf16-plane tensor-core GEMM ----------------
#define GBM 128
#define GBN 64
#define GBK 32
#define ASTR 40
#define BSTR 72
#define A_TILE (GBM*ASTR)
#define B_TILE (GBN*ASTR)
#define STAGE (2*A_TILE + 2*B_TILE)
#define GSMEM (2*STAGE*2)

__device__ __forceinline__ void gemm_load_stage(
    __nv_bfloat16* buf,
    const __nv_bfloat16* __restrict__ Ah, const __nv_bfloat16* __restrict__ Al,
    long a_off, int lda, int M, int m0,
    const __nv_bfloat16* __restrict__ Bh, const __nv_bfloat16* __restrict__ Bl,
    long b_off, int ldb, int n0, int k0, int tid, int three_term, int b_kmajor)
{
    #pragma unroll
    for (int i = 0; i < 4; i++) {
        int e = tid + i * 256;
        int plane = e >> 9;
        if (plane && !three_term) continue;
        int rem = e & 511;
        int m = rem >> 2;
        int seg = rem & 3;
        int mg = m0 + m; if (mg >= M) mg = M - 1;
        const __nv_bfloat16* src = (plane ? Al : Ah) + a_off + (long)mg * lda + k0 + seg * 8;
        cp16(buf + plane * A_TILE + m * ASTR + seg * 8, src);
    }
    if (b_kmajor) {
        #pragma unroll
        for (int i = 0; i < 2; i++) {
            int e = tid + i * 256;
            int plane = e >> 8;
            if (plane && !three_term) continue;
            int rem = e & 255;
            int n = rem >> 2;
            int seg = rem & 3;
            const __nv_bfloat16* src = (plane ? Bl : Bh) + b_off + (long)(n0 + n) * ldb + k0 + seg * 8;
            cp16(buf + 2 * A_TILE + plane * B_TILE + n * ASTR + seg * 8, src);
        }
    } else {
        #pragma unroll
        for (int i = 0; i < 2; i++) {
            int e = tid + i * 256;
            int plane = e >> 8;
            if (plane && !three_term) continue;
            int rem = e & 255;
            int k = rem >> 3;
            int seg = rem & 7;
            const __nv_bfloat16* src = (plane ? Bl : Bh) + b_off + (long)(k0 + k) * ldb + n0 + seg * 8;
            cp16(buf + 2 * A_TILE + plane * B_TILE + k * BSTR + seg * 8, src);
        }
    }
}

__global__ __launch_bounds__(256, 2)
void gemm_planes(
    int M, int N, int K,
    const __nv_bfloat16* __restrict__ Ah, const __nv_bfloat16* __restrict__ Al,
    long a_bo, long a_bi, int lda,
    const __nv_bfloat16* __restrict__ Bh, const __nv_bfloat16* __restrict__ Bl,
    long b_bo, long b_bi, int ldb,
    float* __restrict__ C, __nv_bfloat16* __restrict__ Ch, __nv_bfloat16* __restrict__ Cl,
    long c_bo, long c_bi, int ldc,
    const float* __restrict__ bias, int bias_mode, int three_term, int b_kmajor,
    int z_inner)
{
    extern __shared__ __align__(16) __nv_bfloat16 gsm[];
    const int z  = blockIdx.z;
    const int zo = z / z_inner;
    const int zi = z % z_inner;
    const long a_off = (long)zo * a_bo + (long)zi * a_bi;
    const long b_off = (long)zo * b_bo + (long)zi * b_bi;
    const long c_off = (long)zo * c_bo + (long)zi * c_bi;
    const int m0 = blockIdx.y * GBM;
    const int n0 = blockIdx.x * GBN;
    const int tt = three_term;

    const int tid  = threadIdx.x;
    const int lane = tid & 31;
    const int warp = tid >> 5;
    const int wm = (warp & 3) * 32;
    const int wn = (warp >> 2) * 32;
    const int qr = lane >> 2;
    const int qc = (lane & 3) * 2;
    const int a_row = ((lane >> 3) & 1) * 8 + (lane & 7);
    const int a_col = (lane >> 4) * 8;
    const int b_row = ((lane >> 3) & 1) * 8 + (lane & 7);
    const int b_col = ((lane >> 4) & 1) * 8;
    const int bk_row = ((lane >> 4) & 1) * 8 + (lane & 7);
    const int bk_col = ((lane >> 3) & 1) * 8;

    float acc[2][4][4] = {};

    gemm_load_stage(gsm, Ah, Al, a_off, lda, M, m0, Bh, Bl, b_off, ldb, n0, 0, tid, tt, b_kmajor);
    CP_COMMIT();

    const int nstage = K / GBK;
    for (int s = 0; s < nstage; s++) {
        CP_WAIT0();
        __syncthreads();
        if (s + 1 < nstage) {
            gemm_load_stage(gsm + ((s + 1) & 1) * STAGE,
                            Ah, Al, a_off, lda, M, m0,
                            Bh, Bl, b_off, ldb, n0, (s + 1) * GBK, tid, tt, b_kmajor);
            CP_COMMIT();
        }
        const __nv_bfloat16* As = gsm + (s & 1) * STAGE;
        const __nv_bfloat16* Bs = As + 2 * A_TILE;

        #pragma unroll
        for (int ks = 0; ks < 2; ks++) {
            const int kc = ks * 16;
            uint32_t ah[2][4], al[2][4], bh[2][4], bl[2][4];
            #pragma unroll
            for (int mt = 0; mt < 2; mt++) {
                const __nv_bfloat16* base = As + (wm + mt * 16 + a_row) * ASTR + kc + a_col;
                ldsm4(ah[mt], base);
                if (tt) ldsm4(al[mt], base + A_TILE);
            }
            if (b_kmajor) {
                #pragma unroll
                for (int ng = 0; ng < 2; ng++) {
                    const __nv_bfloat16* base = Bs + (wn + ng * 16 + bk_row) * ASTR + kc + bk_col;
                    ldsm4(bh[ng], base);
                    if (tt) ldsm4(bl[ng], base + B_TILE);
                }
            } else {
                #pragma unroll
                for (int ng = 0; ng < 2; ng++) {
                    const __nv_bfloat16* base = Bs + (kc + b_row) * BSTR + wn + ng * 16 + b_col;
                    ldsm4t(bh[ng], base);
                    if (tt) ldsm4t(bl[ng], base + B_TILE);
                }
            }
            #pragma unroll
            for (int mt = 0; mt < 2; mt++)
                #pragma unroll
                for (int ng = 0; ng < 2; ng++) {
                    mma_bf16(acc[mt][2 * ng    ], ah[mt], bh[ng]);
                    mma_bf16(acc[mt][2 * ng + 1], ah[mt], bh[ng] + 2);
                    if (tt) {
                        mma_bf16(acc[mt][2 * ng    ], al[mt], bh[ng]);
                        mma_bf16(acc[mt][2 * ng    ], ah[mt], bl[ng]);
                        mma_bf16(acc[mt][2 * ng + 1], al[mt], bh[ng] + 2);
                        mma_bf16(acc[mt][2 * ng + 1], ah[mt], bl[ng] + 2);
                    }
                }
        }
    }

    // --- epilogue
    #pragma unroll
    for (int mt = 0; mt < 2; mt++) {
        #pragma unroll
        for (int nt = 0; nt < 4; nt++) {
            int r0 = m0 + wm + mt * 16 + qr;
            int r1 = r0 + 8;
            int c  = n0 + wn + nt * 8 + qc;
            float bn0 = 0.f, bn1 = 0.f;
            if (bias_mode == 1) { bn0 = bias[c]; bn1 = bias[c + 1]; }
            float v00 = acc[mt][nt][0] + bn0;
            float v01 = acc[mt][nt][1] + bn1;
            float v10 = acc[mt][nt][2] + bn0;
            float v11 = acc[mt][nt][3] + bn1;
            if (bias_mode == 2) {
                if (r0 < M) { float bm = bias[r0]; v00 += bm; v01 += bm; }
                if (r1 < M) { float bm = bias[r1]; v10 += bm; v11 += bm; }
            }
            if (Ch && Cl) {
                __nv_bfloat16 h0, l0, h1, l1;
                if (r0 < M) {
                    split_bf16(v00, h0, l0); split_bf16(v01, h1, l1);
                    *(uint32_t*)(Ch + c_off + (long)r0 * ldc + c) = packb(h0, h1);
                    *(uint32_t*)(Cl + c_off + (long)r0 * ldc + c) = packb(l0, l1);
                }
                if (r1 < M) {
                    split_bf16(v10, h0, l0); split_bf16(v11, h1, l1);
                    *(uint32_t*)(Ch + c_off + (long)r1 * ldc + c) = packb(h0, h1);
                    *(uint32_t*)(Cl + c_off + (long)r1 * ldc + c) = packb(l0, l1);
                }
            } else if (Ch) {
                if (r0 < M)
                    *(uint32_t*)(Ch + c_off + (long)r0 * ldc + c) = cvt_bf16x2(v00, v01);
                if (r1 < M)
                    *(uint32_t*)(Ch + c_off + (long)r1 * ldc + c) = cvt_bf16x2(v10, v11);
            } else {
                if (r0 < M) {
                    C[c_off + (long)r0 * ldc + c    ] = v00;
                    C[c_off + (long)r0 * ldc + c + 1] = v01;
                }
                if (r1 < M) {
                    C[c_off + (long)r1 * ldc + c    ] = v10;
                    C[c_off + (long)r1 * ldc + c + 1] = v11;
                }
            }
        }
    }
}

// ---------------- fused flash attention ----------------
#define VKP 72
#define FTILE (64*VKP)
#define NTILES 2
#define NSTAGE 3
#define FSMEM (NSTAGE*NTILES*FTILE*2)

__device__ __forceinline__ void flash_load_chunk(
    __nv_bfloat16* buf,
    const __nv_bfloat16* __restrict__ qh_plane,
    long kbase, long vbase, int c, int tid)
{
    #pragma unroll
    for (int i = 0; i < 8; i++) {
        int e    = tid + i * 128;
        int tile = e >> 9;
        int rem  = e & 511;
        int row  = rem >> 3;
        int seg  = rem & 7;
        long off = ((tile == 0) ? kbase : vbase) + (long)(c * 64 + row) * QKVW + seg * 8;
        cp16(buf + tile * FTILE + row * VKP + seg * 8, qh_plane + off);
    }
}

__global__ __launch_bounds__(128, 4)
void flash_attn(const __nv_bfloat16* __restrict__ qh_plane,
                const float* __restrict__ vsum,
                __nv_bfloat16* __restrict__ combh,
                __nv_bfloat16* __restrict__ combl)
{
    extern __shared__ __align__(16) __nv_bfloat16 sm[];
    const int z = blockIdx.y;
    const int b = z >> 3, h = z & 7;
    const int m0 = blockIdx.x * 64;
    const int tid  = threadIdx.x;
    const int lane = tid & 31;
    const int warp = tid >> 5;
    const int qr = lane >> 2;
    const int qc = (lane & 3) * 2;

    const long zbase = (long)b * SS * QKVW + h * HD;
    const long kbase = zbase + DD;
    const long vbase = zbase + 2 * DD;

    const int r0 = m0 + warp * 16 + qr;
    uint32_t qh[4][4];
    #pragma unroll
    for (int ks = 0; ks < 4; ks++) {
        #pragma unroll
        for (int a = 0; a < 4; a++) {
            int row = r0 + (a & 1) * 8;
            int col = ks * 16 + qc + (a >> 1) * 8;
            qh[ks][a] = *(const uint32_t*)(qh_plane + zbase + (long)row * QKVW + col);
        }
    }

    float o[8][4] = {};
    uint64_t L01 = pk2(0.f, 0.f), L23 = pk2(0.f, 0.f);

    const int skey_off = ((lane >> 4) & 1) * 8 + (lane & 7);
    const int scol_off = ((lane >> 3) & 1) * 8;
    const int vkey_off = ((lane >> 3) & 1) * 8 + (lane & 7);
    const int vcol_off = ((lane >> 4) & 1) * 8;

    flash_load_chunk(sm, qh_plane, kbase, vbase, 0, tid);
    CP_COMMIT();
    flash_load_chunk(sm + NTILES * FTILE, qh_plane, kbase, vbase, 1, tid);
    CP_COMMIT();

    int buf_c = 0;
    for (int c = 0; c < SS / 64; c++) {
        CP_WAIT1();
        __syncthreads();
        const __nv_bfloat16* Kh_ = sm + buf_c * NTILES * FTILE;
        const __nv_bfloat16* Vh_ = Kh_ + FTILE;

        if (c + 2 < SS / 64) {
            int buf_n = buf_c + 2; if (buf_n >= NSTAGE) buf_n -= NSTAGE;
            flash_load_chunk(sm + buf_n * NTILES * FTILE,
                             qh_plane, kbase, vbase, c + 2, tid);
        }
        CP_COMMIT();

        // --- S = Q K^T (1-term; pre-scaled)
        float s[8][4] = {};
        #pragma unroll
        for (int ks = 0; ks < 4; ks++) {
            const int kc = ks * 16;
            #pragma unroll
            for (int ntp = 0; ntp < 4; ntp++) {
                const __nv_bfloat16* base = Kh_ + (ntp * 16 + skey_off) * VKP + kc + scol_off;
                uint32_t bh[4];
                ldsm4(bh, base);
                mma_bf16(s[2 * ntp    ], qh[ks], bh);
                mma_bf16(s[2 * ntp + 1], qh[ks], bh + 2);
            }
        }

        // --- t = expm1(s) via packed f32x2 poly
        uint32_t ph[4][4];
        #pragma unroll
        for (int nt = 0; nt < 8; nt++) {
            uint64_t x01 = pk2(s[nt][0], s[nt][1]);
            uint64_t x23 = pk2(s[nt][2], s[nt][3]);
            uint64_t t01 = expm1_poly2(x01);
            uint64_t t23 = expm1_poly2(x23);
            L01 = add2(L01, t01);
            L23 = add2(L23, t23);
            int ks = nt >> 1, off = (nt & 1) * 2;
            ph[ks][off    ] = cvt_bf16x2_p(t01);
            ph[ks][off + 1] = cvt_bf16x2_p(t23);
        }

        // --- O += T V (1-term)
        #pragma unroll
        for (int ks = 0; ks < 4; ks++) {
            const int kc = ks * 16;
            #pragma unroll
            for (int ntp = 0; ntp < 4; ntp++) {
                const __nv_bfloat16* base = Vh_ + (kc + vkey_off) * VKP + ntp * 16 + vcol_off;
                uint32_t vh4[4];
                ldsm4t(vh4, base);
                mma_bf16(o[2 * ntp    ], ph[ks], vh4);
                mma_bf16(o[2 * ntp + 1], ph[ks], vh4 + 2);
            }
        }
        if (++buf_c >= NSTAGE) buf_c = 0;
    }

    // --- reduce, normalize, write
    float a0, a1, b0, b1;
    unpk2(L01, a0, a1);
    unpk2(L23, b0, b1);
    float l0r = a0 + a1, l1r = b0 + b1;
    l0r += __shfl_xor_sync(0xffffffff, l0r, 1);
    l0r += __shfl_xor_sync(0xffffffff, l0r, 2);
    l1r += __shfl_xor_sync(0xffffffff, l1r, 1);
    l1r += __shfl_xor_sync(0xffffffff, l1r, 2);
    float inv0 = 1.f / (l0r + (float)SS), inv1 = 1.f / (l1r + (float)SS);
    const float* vs = vsum + z * HD;
    const long cbase = (long)b * SS * DD + h * HD;
    #pragma unroll
    for (int nt = 0; nt < 8; nt++) {
        int col = nt * 8 + qc;
        float vs0 = vs[col], vs1 = vs[col + 1];
        __nv_bfloat16 h0, l0, h1, l1;
        split_bf16((o[nt][0] + vs0) * inv0, h0, l0);
        split_bf16((o[nt][1] + vs1) * inv0, h1, l1);
        *(uint32_t*)(combh + cbase + (long)r0 * DD + col) = packb(h0, h1);
        *(uint32_t*)(combl + cbase + (long)r0 * DD + col) = packb(l0, l1);
        split_bf16((o[nt][2] + vs0) * inv1, h0, l0);
        split_bf16((o[nt][3] + vs1) * inv1, h1, l1);
        *(uint32_t*)(combh + cbase + (long)(r0 + 8) * DD + col) = packb(h0, h1);
        *(uint32_t*)(combl + cbase + (long)(r0 + 8) * DD + col) = packb(l0, l1);
    }
}

// ---------------- launch ----------------
extern "C" void kernel_launch(void* const* d_in, const int* in_sizes, int n_in,
                              void* d_out, int out_size)
{
    (void)in_sizes; (void)n_in; (void)out_size;
    const float* x  = (const float*)d_in[0];
    const float* Wq = (const float*)d_in[1];
    const float* bq = (const float*)d_in[2];
    const float* Wk = (const float*)d_in[3];
    const float* bk = (const float*)d_in[4];
    const float* Wv = (const float*)d_in[5];
    const float* bv = (const float*)d_in[6];
    const float* Wt = (const float*)d_in[7];
    const float* bt = (const float*)d_in[8];
    const float* Wo = (const float*)d_in[9];
    const float* bo = (const float*)d_in[10];
    float* out = (float*)d_out;

    __nv_bfloat16 *qkvh, *combh, *combl, *uph, *upl;
    __nv_bfloat16 *xh, *wph, *wth, *wtl, *woh, *wol;
    float *bp, *vsum, *xpart, *scr;
    cudaGetSymbolAddress((void**)&qkvh,  g_qkvh);
    cudaGetSymbolAddress((void**)&combh, g_combh);
    cudaGetSymbolAddress((void**)&combl, g_combl);
    cudaGetSymbolAddress((void**)&uph,   g_uph);
    cudaGetSymbolAddress((void**)&upl,   g_upl);
    cudaGetSymbolAddress((void**)&xh,    g_xh);
    cudaGetSymbolAddress((void**)&wph,   g_wph);
    cudaGetSymbolAddress((void**)&wth,   g_wth);
    cudaGetSymbolAddress((void**)&wtl,   g_wtl);
    cudaGetSymbolAddress((void**)&woh,   g_woh);
    cudaGetSymbolAddress((void**)&wol,   g_wol);
    cudaGetSymbolAddress((void**)&bp,    g_bp);
    cudaGetSymbolAddress((void**)&vsum,  g_vsum);
    cudaGetSymbolAddress((void**)&xpart, g_xpart);
    cudaGetSymbolAddress((void**)&scr,   g_scr);

    static cudaStream_t s2 = nullptr;
    static cudaEvent_t evF = nullptr, evV = nullptr, evJ = nullptr;
    static bool attr_set = false;
    if (!attr_set) {
        cudaFuncSetAttribute(flash_attn,
            cudaFuncAttributeMaxDynamicSharedMemorySize, FSMEM);
        cudaFuncSetAttribute(gemm_planes,
            cudaFuncAttributeMaxDynamicSharedMemorySize, GSMEM);
        cudaStreamCreateWithFlags(&s2, cudaStreamNonBlocking);
        cudaEventCreateWithFlags(&evF, cudaEventDisableTiming);
        cudaEventCreateWithFlags(&evV, cudaEventDisableTiming);
        cudaEventCreateWithFlags(&evJ, cudaEventDisableTiming);
        attr_set = true;
    }

    // fork: exact vsum path + Wt/Wo packs on side stream
    cudaEventRecord(evF, 0);
    cudaStreamWaitEvent(s2, evF, 0);
    xsum_part<<<BB * 8, 256, 0, s2>>>(x, xpart);
    vsum2_kernel<<<BB * HH, 256, 0, s2>>>(xpart, Wv, bv, vsum);
    cudaEventRecord(evV, s2);
    pack_split4<<<(PP * SS / 4 + 255) / 256, 256, 0, s2>>>(Wt, wth, wtl, PP * SS / 4);
    pack_split4<<<(II * DD / 4 + 255) / 256, 256, 0, s2>>>(Wo, woh, wol, II * DD / 4);
    cudaEventRecord(evJ, s2);

    // main stream: hi-only packs
    pack_split4_h<<<(NT * II / 4 + 255) / 256, 256>>>(x, xh, NT * II / 4);
    pack_qkv_w<<<(3 * II * DD / 4 + 255) / 256, 256>>>(Wq, Wk, Wv, wph);
    pack_qkv_b<<<(QKVW + 255) / 256, 256>>>(bq, bk, bv, bp);

    // 1) merged QKV projection -> qkvh (hi-only), uniform 1-term
    {
        dim3 grid(QKVW / GBN, NT / GBM, 1);
        gemm_planes<<<grid, 256, GSMEM>>>(NT, QKVW, II,
            xh, xh, 0, 0, II,
            wph, wph, 0, 0, QKVW,
            nullptr, qkvh, nullptr, 0, 0, QKVW,
            bp, 1, 0, 0, 1);
    }

    // join exact vsum before flash
    cudaStreamWaitEvent(0, evV, 0);

    // 2) fused attention -> comb planes [B,S,D]
    {
        dim3 grid(SS / 64, BB * HH);
        flash_attn<<<grid, 128, FSMEM>>>(qkvh, vsum, combh, combl);
    }

    // join Wt/Wo packs before tail GEMMs
    cudaStreamWaitEvent(0, evJ, 0);

    // 3) temporal (3-term), split-K=2 -> fp32 scratch partials
    {
        dim3 grid(DD / GBN, (PP + GBM - 1) / GBM, BB * 2);
        gemm_planes<<<grid, 256, GSMEM>>>(PP, DD, SS / 2,
            wth, wtl, 0, SS / 2, SS,
            combh, combl, (long)SS * DD, (long)(SS / 2) * DD, DD,
            scr, nullptr, nullptr, (long)PP * DD, (long)BB * PP * DD, DD,
            nullptr, 0, 1, 0, 2);
    }
    up_pack<<<(BB * PP * DD / 4 + 255) / 256, 256>>>(scr, bt, uph, upl);

    // 4) out (3-term, B k-major), split-K=2 -> fp32 scratch partials
    {
        dim3 grid(II / GBN, (PP + GBM - 1) / GBM, BB * 2);
        gemm_planes<<<grid, 256, GSMEM>>>(PP, II, DD / 2,
            uph, upl, (long)PP * DD, DD / 2, DD,
            woh, wol, 0, DD / 2, DD,
            scr, nullptr, nullptr, (long)PP * II, (long)BB * PP * II, II,
            nullptr, 0, 1, 1, 2);
    }
    out_final<<<(BB * PP * II / 4 + 255) / 256, 256>>>(scr, bo, out);
}